// round 12
// baseline (speedup 1.0000x reference)
#include <cuda_runtime.h>
#include <cuda_bf16.h>

// Problem constants
#define Bn 4
#define Ln 8
#define Nn 4096
#define Mn 2048
#define Kn 32
#define Sn 8
#define Jn 3

// Staging buffers (device globals; no runtime allocation)
__device__ float g_anchors[Bn * Sn * Mn * 3];
__device__ float g_P[Bn * 8 * Nn * 64];
__device__ float g_A[Bn * Sn * Mn * 64];
__device__ int   g_idx[Bn * Sn * Jn * Mn * Kn];
__device__ float g_hmax[Bn * Sn * Jn * Mn * 128];        // [combo][m][r]
__device__ __nv_bfloat16 g_Ws1hi[128 * 64];              // Ws1 hi, [r][k] row-major
__device__ unsigned g_WsFragLo[8 * 4 * 32 * 4];          // Ws1 lo in mma A-frag layout
__device__ unsigned g_WtFragHi[3 * 16 * 8 * 32 * 4];     // Wt hi in mma A-frag layout
__device__ unsigned g_WtFragLo[3 * 16 * 8 * 32 * 4];     // Wt lo

// ---------------------------------------------------------------------------
// packed f32x2 helpers (per-lane IEEE rn — identical to __fadd_rn/__fmul_rn)
// ---------------------------------------------------------------------------
__device__ __forceinline__ unsigned long long f2pack(float lo, float hi) {
    unsigned long long r;
    asm("mov.b64 %0, {%1, %2};" : "=l"(r) : "f"(lo), "f"(hi));
    return r;
}
__device__ __forceinline__ void f2unpack(float& lo, float& hi, unsigned long long v) {
    asm("mov.b64 {%0, %1}, %2;" : "=f"(lo), "=f"(hi) : "l"(v));
}
__device__ __forceinline__ unsigned long long f2add(unsigned long long a,
                                                    unsigned long long b) {
    unsigned long long r;
    asm("add.rn.f32x2 %0, %1, %2;" : "=l"(r) : "l"(a), "l"(b));
    return r;
}
__device__ __forceinline__ unsigned long long f2mul(unsigned long long a,
                                                    unsigned long long b) {
    unsigned long long r;
    asm("mul.rn.f32x2 %0, %1, %2;" : "=l"(r) : "l"(a), "l"(b));
    return r;
}

// ---------------------------------------------------------------------------
// K1 (merged): blocks 0-31: FPS. blocks 32-543: P projection.
// blocks 544-735: wtfrag hi. blocks 736-927: wtfrag lo. blocks 928-959: Ws1 prep.
// All non-fps work is fps-independent and rides in fps's shadow (fps uses
// only 32 SMs for ~600us).
// ---------------------------------------------------------------------------
__global__ void __launch_bounds__(256) fps_prep_kernel(
    const float* __restrict__ xyzs, float* __restrict__ out_xyz,
    const float* __restrict__ feats, const float* __restrict__ Ws0,
    const float* __restrict__ Ws1, const float* __restrict__ Wt) {
    int t = threadIdx.x;
    int blk = blockIdx.x;

    if (blk < 32) {
        // ---------------- FPS (R10/R11 version, unchanged) ----------------
        int bs = blk;
        const float* xyz = xyzs + (size_t)bs * Nn * 3;
        __shared__ unsigned long long skey[2][8];

        int lane = t & 31, wid = t >> 5;

        unsigned long long pxx[8], pyy[8], pzz[8];
        float pd[16];
#pragma unroll
        for (int i = 0; i < 8; i++) {
            int p0 = t + (2 * i) * 256;
            int p1 = t + (2 * i + 1) * 256;
            pxx[i] = f2pack(xyz[3 * p0], xyz[3 * p1]);
            pyy[i] = f2pack(xyz[3 * p0 + 1], xyz[3 * p1 + 1]);
            pzz[i] = f2pack(xyz[3 * p0 + 2], xyz[3 * p1 + 2]);
            pd[2 * i] = 1e10f;
            pd[2 * i + 1] = 1e10f;
        }
        float cx = xyz[0], cy = xyz[1], cz = xyz[2];

        float* oanc = g_anchors + (size_t)bs * Mn * 3;
        float* oxyz = out_xyz + (size_t)bs * Mn * 3;

        for (int m = 0; m < Mn; m++) {
            if (t == 0) {
                oanc[3 * m] = cx; oanc[3 * m + 1] = cy; oanc[3 * m + 2] = cz;
                oxyz[3 * m] = cx; oxyz[3 * m + 1] = cy; oxyz[3 * m + 2] = cz;
            }
            unsigned long long vcx = f2pack(-cx, -cx);
            unsigned long long vcy = f2pack(-cy, -cy);
            unsigned long long vcz = f2pack(-cz, -cz);
            unsigned long long key = 0;
#pragma unroll
            for (int i = 0; i < 8; i++) {
                unsigned long long dx = f2add(pxx[i], vcx);
                unsigned long long dy = f2add(pyy[i], vcy);
                unsigned long long dz = f2add(pzz[i], vcz);
                unsigned long long ssum =
                    f2add(f2add(f2mul(dx, dx), f2mul(dy, dy)), f2mul(dz, dz));
                float d0, d1;
                f2unpack(d0, d1, ssum);
                float nd0 = fminf(pd[2 * i], d0);
                float nd1 = fminf(pd[2 * i + 1], d1);
                pd[2 * i] = nd0;
                pd[2 * i + 1] = nd1;
                unsigned long long k0 =
                    ((unsigned long long)__float_as_uint(nd0) << 32) |
                    (unsigned)(0xFFFFFFFFu - (unsigned)(t + (2 * i) * 256));
                unsigned long long k1 =
                    ((unsigned long long)__float_as_uint(nd1) << 32) |
                    (unsigned)(0xFFFFFFFFu - (unsigned)(t + (2 * i + 1) * 256));
                key = (k0 > key) ? k0 : key;
                key = (k1 > key) ? k1 : key;
            }
#pragma unroll
            for (int off = 16; off > 0; off >>= 1) {
                unsigned long long k2 = __shfl_xor_sync(0xffffffffu, key, off);
                key = (k2 > key) ? k2 : key;
            }
            if (lane == 0) skey[m & 1][wid] = key;
            __syncthreads();
            unsigned long long kb = skey[m & 1][0];
#pragma unroll
            for (int wq = 1; wq < 8; wq++) {
                unsigned long long k2 = skey[m & 1][wq];
                kb = (k2 > kb) ? k2 : kb;
            }
            int widx = (int)(0xFFFFFFFFu - (unsigned)kb);
            cx = xyz[3 * widx]; cy = xyz[3 * widx + 1]; cz = xyz[3 * widx + 2];
        }
    } else if (blk < 544) {
        // ---------------- P projection ----------------
        __shared__ float w[64 * 6];
        for (int i = t; i < 64 * 6; i += 256) w[i] = Ws0[i];
        __syncthreads();

        int gp = (blk - 32) * 256 + t;
        int n = gp & (Nn - 1);
        int bf = gp >> 12;
        const float* p = xyzs + (size_t)gp * 3;
        float x = p[0], y = p[1], z = p[2];
        const float* f = feats + (size_t)bf * 3 * Nn + n;
        float f0 = f[0], f1 = f[Nn], f2 = f[2 * Nn];
        float4* o = (float4*)(g_P + (size_t)gp * 64);
#pragma unroll
        for (int oo = 0; oo < 64; oo += 4) {
            float4 r;
            const float* w0 = w + oo * 6;
            r.x = w0[0] * x + w0[1] * y + w0[2] * z + w0[3] * f0 + w0[4] * f1 + w0[5] * f2;
            r.y = w0[6] * x + w0[7] * y + w0[8] * z + w0[9] * f0 + w0[10] * f1 + w0[11] * f2;
            r.z = w0[12] * x + w0[13] * y + w0[14] * z + w0[15] * f0 + w0[16] * f1 + w0[17] * f2;
            r.w = w0[18] * x + w0[19] * y + w0[20] * z + w0[21] * f0 + w0[22] * f1 + w0[23] * f2;
            o[oo >> 2] = r;
        }
    } else if (blk < 736) {
        // ---------------- wtfrag hi ----------------
        int i = (blk - 544) * 256 + t;
        int q = i & 3, lane = (i >> 2) & 31, ks = (i >> 7) & 7, rb = (i >> 10) & 15, j = i >> 14;
        int row = rb * 16 + (lane >> 2) + (q & 1) * 8;
        int k = ks * 16 + (lane & 3) * 2 + ((q >> 1) & 1) * 8;
        float e0 = Wt[(j * 256 + row) * 128 + k];
        float e1 = Wt[(j * 256 + row) * 128 + k + 1];
        __nv_bfloat16 h0 = __float2bfloat16_rn(e0);
        __nv_bfloat16 h1 = __float2bfloat16_rn(e1);
        unsigned u0 = *(unsigned short*)&h0, u1 = *(unsigned short*)&h1;
        g_WtFragHi[i] = (u1 << 16) | u0;
    } else if (blk < 928) {
        // ---------------- wtfrag lo ----------------
        int i = (blk - 736) * 256 + t;
        int q = i & 3, lane = (i >> 2) & 31, ks = (i >> 7) & 7, rb = (i >> 10) & 15, j = i >> 14;
        int row = rb * 16 + (lane >> 2) + (q & 1) * 8;
        int k = ks * 16 + (lane & 3) * 2 + ((q >> 1) & 1) * 8;
        float e0 = Wt[(j * 256 + row) * 128 + k];
        float e1 = Wt[(j * 256 + row) * 128 + k + 1];
        __nv_bfloat16 h0 = __float2bfloat16_rn(e0);
        __nv_bfloat16 h1 = __float2bfloat16_rn(e1);
        __nv_bfloat16 l0 = __float2bfloat16_rn(e0 - __bfloat162float(h0));
        __nv_bfloat16 l1 = __float2bfloat16_rn(e1 - __bfloat162float(h1));
        unsigned u0 = *(unsigned short*)&l0, u1 = *(unsigned short*)&l1;
        g_WtFragLo[i] = (u1 << 16) | u0;
    } else {
        // ---------------- Ws1 prep ----------------
        int i = (blk - 928) * 256 + t;  // < 8192
        if (i < 128 * 64) {
            g_Ws1hi[i] = __float2bfloat16_rn(Ws1[i]);
        }
        if (i < 8 * 4 * 32 * 4) {
            int q = i & 3, lane = (i >> 2) & 31, ks = (i >> 7) & 3, w8 = i >> 9;
            int row = w8 * 16 + (lane >> 2) + (q & 1) * 8;
            int k = ks * 16 + (lane & 3) * 2 + ((q >> 1) & 1) * 8;
            float e0 = Ws1[row * 64 + k];
            float e1 = Ws1[row * 64 + k + 1];
            __nv_bfloat16 h0 = __float2bfloat16_rn(e0);
            __nv_bfloat16 h1 = __float2bfloat16_rn(e1);
            __nv_bfloat16 l0 = __float2bfloat16_rn(e0 - __bfloat162float(h0));
            __nv_bfloat16 l1 = __float2bfloat16_rn(e1 - __bfloat162float(h1));
            unsigned ul0 = *(unsigned short*)&l0, ul1 = *(unsigned short*)&l1;
            g_WsFragLo[i] = (ul1 << 16) | ul0;
        }
    }
}

// ---------------------------------------------------------------------------
// K2 (merged): blockIdx.y < 96: ball query (f32x2 distance math, 4 pts/lane).
// blockIdx.y == 96: A projection (depends only on fps, like bq).
// ---------------------------------------------------------------------------
__global__ void __launch_bounds__(256) ball_query_A_kernel(
    const float* __restrict__ xyzs, const float* __restrict__ Ws0) {
    int t = threadIdx.x;
    if (blockIdx.y == 96) {
        // ---------------- A projection ----------------
        __shared__ float w[64 * 3];
        for (int i = t; i < 64 * 3; i += 256) {
            int o = i / 3, c = i % 3;
            w[i] = Ws0[o * 6 + c];
        }
        __syncthreads();
        int ga = blockIdx.x * 256 + t;  // 0..65535
        const float* a = g_anchors + (size_t)ga * 3;
        float x = a[0], y = a[1], z = a[2];
        float4* o = (float4*)(g_A + (size_t)ga * 64);
#pragma unroll
        for (int oo = 0; oo < 64; oo += 4) {
            float4 r;
            const float* w0 = w + oo * 3;
            r.x = w0[0] * x + w0[1] * y + w0[2] * z;
            r.y = w0[3] * x + w0[4] * y + w0[5] * z;
            r.z = w0[6] * x + w0[7] * y + w0[8] * z;
            r.w = w0[9] * x + w0[10] * y + w0[11] * z;
            o[oo >> 2] = r;
        }
        return;
    }

    // ---------------- ball query ----------------
    int combo = blockIdx.y;
    int j = combo % 3;
    int bs = combo / 3;
    int b = bs >> 3, s = bs & 7;
    int g = s - 1 + j;
    g = g < 0 ? 0 : (g > 7 ? 7 : g);
    int wid = t >> 5, lane = t & 31;
    int m = blockIdx.x * 8 + wid;

    const float* pts = xyzs + (size_t)(b * 8 + g) * Nn * 3;
    const float* anc = g_anchors + ((size_t)bs * Mn + m) * 3;
    float ax = anc[0], ay = anc[1], az = anc[2];
    int* out = g_idx + ((size_t)combo * Mn + m) * Kn;

    unsigned long long nax2 = f2pack(-ax, -ax);
    unsigned long long nay2 = f2pack(-ay, -ay);
    unsigned long long naz2 = f2pack(-az, -az);

    int found = 0, first = -1;
    unsigned lt = (1u << lane) - 1u;
    for (int base = 0; base < Nn && found < Kn; base += 128) {
        int n0 = base + 4 * lane;
        const float4* pp = (const float4*)(pts + 3 * n0);
        float4 v0 = pp[0];  // x0 y0 z0 x1
        float4 v1 = pp[1];  // y1 z1 x2 y2
        float4 v2 = pp[2];  // z2 x3 y3 z3

        // pts 0,1 packed; pts 2,3 packed (per-lane rn == scalar __f*_rn)
        unsigned long long dx, dy, dz, ssum;
        dx = f2add(f2pack(v0.x, v0.w), nax2);
        dy = f2add(f2pack(v0.y, v1.x), nay2);
        dz = f2add(f2pack(v0.z, v1.y), naz2);
        ssum = f2add(f2add(f2mul(dx, dx), f2mul(dy, dy)), f2mul(dz, dz));
        float d0, d1;
        f2unpack(d0, d1, ssum);
        dx = f2add(f2pack(v1.z, v2.y), nax2);
        dy = f2add(f2pack(v1.w, v2.z), nay2);
        dz = f2add(f2pack(v2.x, v2.w), naz2);
        ssum = f2add(f2add(f2mul(dx, dx), f2mul(dy, dy)), f2mul(dz, dz));
        float d2, d3;
        f2unpack(d2, d3, ssum);

        bool p0 = d0 < 0.25f, p1 = d1 < 0.25f, p2 = d2 < 0.25f, p3 = d3 < 0.25f;
        unsigned m0 = __ballot_sync(0xffffffffu, p0);
        unsigned m1 = __ballot_sync(0xffffffffu, p1);
        unsigned m2 = __ballot_sync(0xffffffffu, p2);
        unsigned m3 = __ballot_sync(0xffffffffu, p3);

        if (first < 0 && (m0 | m1 | m2 | m3)) {
            int c0 = m0 ? 4 * (__ffs(m0) - 1) + 0 : 0x7fffffff;
            int c1 = m1 ? 4 * (__ffs(m1) - 1) + 1 : 0x7fffffff;
            int c2 = m2 ? 4 * (__ffs(m2) - 1) + 2 : 0x7fffffff;
            int c3 = m3 ? 4 * (__ffs(m3) - 1) + 3 : 0x7fffffff;
            int cmin = c0 < c1 ? c0 : c1;
            cmin = c2 < cmin ? c2 : cmin;
            cmin = c3 < cmin ? c3 : cmin;
            first = base + cmin;
        }
        int pos = found + __popc(m0 & lt) + __popc(m1 & lt) +
                  __popc(m2 & lt) + __popc(m3 & lt);
        if (p0 && pos < Kn) out[pos] = n0;
        pos += p0 ? 1 : 0;
        if (p1 && pos < Kn) out[pos] = n0 + 1;
        pos += p1 ? 1 : 0;
        if (p2 && pos < Kn) out[pos] = n0 + 2;
        pos += p2 ? 1 : 0;
        if (p3 && pos < Kn) out[pos] = n0 + 3;
        found += __popc(m0) + __popc(m1) + __popc(m2) + __popc(m3);
    }
    if (found < Kn) {
        int pad = first < 0 ? 0 : first;
        for (int p = found + lane; p < Kn; p += 32) out[p] = pad;
    }
}

// ---------------------------------------------------------------------------
// mma / ldsm helpers
// ---------------------------------------------------------------------------
__device__ __forceinline__ void mma_bf16(float c[4], const unsigned a[4],
                                         unsigned b0, unsigned b1) {
    asm volatile(
        "mma.sync.aligned.m16n8k16.row.col.f32.bf16.bf16.f32 "
        "{%0,%1,%2,%3}, {%4,%5,%6,%7}, {%8,%9}, {%0,%1,%2,%3};"
        : "+f"(c[0]), "+f"(c[1]), "+f"(c[2]), "+f"(c[3])
        : "r"(a[0]), "r"(a[1]), "r"(a[2]), "r"(a[3]), "r"(b0), "r"(b1));
}

__device__ __forceinline__ void ldsm4(unsigned r[4], unsigned saddr) {
    asm volatile(
        "ldmatrix.sync.aligned.m8n8.x4.shared.b16 {%0,%1,%2,%3}, [%4];"
        : "=r"(r[0]), "=r"(r[1]), "=r"(r[2]), "=r"(r[3])
        : "r"(saddr));
}

// ---------------------------------------------------------------------------
// K3: mlp (R11 structure — 32x32 warp tile, halved B reads; REPS=16)
// ---------------------------------------------------------------------------
#define MLP_REPS 16

__global__ void __launch_bounds__(256, 2) mlp_kernel() {
    __shared__ __align__(16) __nv_bfloat16 Whi[128 * 64];
    __shared__ __align__(16) __nv_bfloat16 Bhs[2][64 * 64];
    __shared__ __align__(16) __nv_bfloat16 Bls[2][64 * 64];

    int t = threadIdx.x;
    int lane = t & 31, w = t >> 5;
    int mt = w >> 1;
    int nh = w & 1;
    int combo = blockIdx.y;
    int j = combo % 3;
    int bs = combo / 3;
    int b = bs >> 3, s = bs & 7;
    int g = s - 1 + j;
    g = g < 0 ? 0 : (g > 7 ? 7 : g);

    {
        const uint4* gh = (const uint4*)g_Ws1hi;
        uint4* sh = (uint4*)Whi;
        for (int i = t; i < 1024; i += 256) {
            int r = i >> 3, c = i & 7;
            sh[(r << 3) + (c ^ (r & 7))] = gh[i];
        }
    }
    __syncthreads();

    unsigned sWhi = (unsigned)__cvta_generic_to_shared(Whi);
    unsigned sBh0 = (unsigned)__cvta_generic_to_shared(Bhs[0]);
    unsigned sBl0 = (unsigned)__cvta_generic_to_shared(Bls[0]);

    unsigned ahi[2][4][4];
#pragma unroll
    for (int mi = 0; mi < 2; mi++) {
        int r = mt * 32 + mi * 16 + (lane & 15);
#pragma unroll
        for (int ks = 0; ks < 4; ks++) {
            int chunk = ks * 2 + (lane >> 4);
            ldsm4(ahi[mi][ks], sWhi + r * 128 + ((chunk ^ (r & 7)) << 4));
        }
    }

    int col = t & 63;
    int kq = t >> 6;
    int brow_base = (lane & 7) + ((lane & 16) >> 1);
    int bksel = (lane >> 3) & 1;

    const float4* Pbase = (const float4*)(g_P + (size_t)(b * 8 + g) * Nn * 64);
    const float4* Abase = (const float4*)(g_A + (size_t)bs * Mn * 64);
    const int* idxbase = g_idx + (size_t)combo * Mn * Kn;
    const uint4* fragLoV = (const uint4*)g_WsFragLo;

    float4 pf_p[4];
    int mcur;

    {
        int gcol = blockIdx.x * MLP_REPS * 64 + col;
        mcur = gcol >> 5;
        int knb = gcol & 31;
        int n = idxbase[mcur * Kn + knb];
        const float4* Prow = Pbase + (size_t)n * 16;
#pragma unroll
        for (int q = 0; q < 4; q++) pf_p[q] = Prow[kq * 4 + q];
    }
    {
        const float4* Arow = Abase + (size_t)mcur * 16;
        char* bh = (char*)Bhs[0];
        char* bl = (char*)Bls[0];
#pragma unroll
        for (int q = 0; q < 4; q++) {
            float4 a4 = Arow[kq * 4 + q];
            float h0 = fmaxf(pf_p[q].x - a4.x, 0.f);
            float h1 = fmaxf(pf_p[q].y - a4.y, 0.f);
            float h2 = fmaxf(pf_p[q].z - a4.z, 0.f);
            float h3 = fmaxf(pf_p[q].w - a4.w, 0.f);
            __nv_bfloat162 hiA, hiB, loA, loB;
            hiA.x = __float2bfloat16_rn(h0); hiA.y = __float2bfloat16_rn(h1);
            hiB.x = __float2bfloat16_rn(h2); hiB.y = __float2bfloat16_rn(h3);
            loA.x = __float2bfloat16_rn(h0 - __bfloat162float(hiA.x));
            loA.y = __float2bfloat16_rn(h1 - __bfloat162float(hiA.y));
            loB.x = __float2bfloat16_rn(h2 - __bfloat162float(hiB.x));
            loB.y = __float2bfloat16_rn(h3 - __bfloat162float(hiB.y));
            int k0 = kq * 16 + q * 4;
            int chunk = k0 >> 3;
            int off = col * 128 + ((chunk ^ (col & 7)) << 4) + ((k0 & 7) << 1);
            uint2 vh, vl;
            vh.x = *(unsigned*)&hiA; vh.y = *(unsigned*)&hiB;
            vl.x = *(unsigned*)&loA; vl.y = *(unsigned*)&loB;
            *(uint2*)(bh + off) = vh;
            *(uint2*)(bl + off) = vl;
        }
    }
    __syncthreads();

    for (int rep = 0; rep < MLP_REPS; rep++) {
        int buf = rep & 1;
        int mnext = mcur;
        if (rep + 1 < MLP_REPS) {
            int gcol = (blockIdx.x * MLP_REPS + rep + 1) * 64 + col;
            mnext = gcol >> 5;
            int knb = gcol & 31;
            int n = idxbase[mnext * Kn + knb];
            const float4* Prow = Pbase + (size_t)n * 16;
#pragma unroll
            for (int q = 0; q < 4; q++) pf_p[q] = Prow[kq * 4 + q];
        }

        float acc[2][4][4];
#pragma unroll
        for (int mi = 0; mi < 2; mi++)
#pragma unroll
            for (int nt = 0; nt < 4; nt++)
#pragma unroll
                for (int i = 0; i < 4; i++) acc[mi][nt][i] = 0.f;

        unsigned sBh = sBh0 + buf * 8192;
        unsigned sBl = sBl0 + buf * 8192;
#pragma unroll
        for (int ks = 0; ks < 4; ks++) {
            uint4 fl0 = fragLoV[((mt * 2 + 0) * 4 + ks) * 32 + lane];
            uint4 fl1 = fragLoV[((mt * 2 + 1) * 4 + ks) * 32 + lane];
            unsigned alo0[4] = {fl0.x, fl0.y, fl0.z, fl0.w};
            unsigned alo1[4] = {fl1.x, fl1.y, fl1.z, fl1.w};
            int chunk = ks * 2 + bksel;
#pragma unroll
            for (int p = 0; p < 2; p++) {
                int r = nh * 32 + p * 16 + brow_base;
                unsigned off = r * 128 + ((chunk ^ (r & 7)) << 4);
                unsigned hh[4], ll[4];
                ldsm4(hh, sBh + off);
                ldsm4(ll, sBl + off);
                mma_bf16(acc[0][2 * p],     ahi[0][ks], hh[0], hh[1]);
                mma_bf16(acc[0][2 * p + 1], ahi[0][ks], hh[2], hh[3]);
                mma_bf16(acc[1][2 * p],     ahi[1][ks], hh[0], hh[1]);
                mma_bf16(acc[1][2 * p + 1], ahi[1][ks], hh[2], hh[3]);
                mma_bf16(acc[0][2 * p],     ahi[0][ks], ll[0], ll[1]);
                mma_bf16(acc[0][2 * p + 1], ahi[0][ks], ll[2], ll[3]);
                mma_bf16(acc[1][2 * p],     ahi[1][ks], ll[0], ll[1]);
                mma_bf16(acc[1][2 * p + 1], ahi[1][ks], ll[2], ll[3]);
                mma_bf16(acc[0][2 * p],     alo0,       hh[0], hh[1]);
                mma_bf16(acc[0][2 * p + 1], alo0,       hh[2], hh[3]);
                mma_bf16(acc[1][2 * p],     alo1,       hh[0], hh[1]);
                mma_bf16(acc[1][2 * p + 1], alo1,       hh[2], hh[3]);
            }
        }

        if (rep + 1 < MLP_REPS) {
            const float4* Arow = Abase + (size_t)mnext * 16;
            char* bh = (char*)Bhs[buf ^ 1];
            char* bl = (char*)Bls[buf ^ 1];
#pragma unroll
            for (int q = 0; q < 4; q++) {
                float4 a4 = Arow[kq * 4 + q];
                float h0 = fmaxf(pf_p[q].x - a4.x, 0.f);
                float h1 = fmaxf(pf_p[q].y - a4.y, 0.f);
                float h2 = fmaxf(pf_p[q].z - a4.z, 0.f);
                float h3 = fmaxf(pf_p[q].w - a4.w, 0.f);
                __nv_bfloat162 hiA, hiB, loA, loB;
                hiA.x = __float2bfloat16_rn(h0); hiA.y = __float2bfloat16_rn(h1);
                hiB.x = __float2bfloat16_rn(h2); hiB.y = __float2bfloat16_rn(h3);
                loA.x = __float2bfloat16_rn(h0 - __bfloat162float(hiA.x));
                loA.y = __float2bfloat16_rn(h1 - __bfloat162float(hiA.y));
                loB.x = __float2bfloat16_rn(h2 - __bfloat162float(hiB.x));
                loB.y = __float2bfloat16_rn(h3 - __bfloat162float(hiB.y));
                int k0 = kq * 16 + q * 4;
                int chunk = k0 >> 3;
                int off = col * 128 + ((chunk ^ (col & 7)) << 4) + ((k0 & 7) << 1);
                uint2 vh, vl;
                vh.x = *(unsigned*)&hiA; vh.y = *(unsigned*)&hiB;
                vl.x = *(unsigned*)&loA; vl.y = *(unsigned*)&loB;
                *(uint2*)(bh + off) = vh;
                *(uint2*)(bl + off) = vl;
            }
        }
        mcur = mnext;

        int mbase = (blockIdx.x * MLP_REPS + rep) * 2;
        int grp = lane >> 2;
#pragma unroll
        for (int mi = 0; mi < 2; mi++) {
            float m0 = -1e30f, m1 = -1e30f;
#pragma unroll
            for (int nt = 0; nt < 4; nt++) {
                m0 = fmaxf(m0, fmaxf(acc[mi][nt][0], acc[mi][nt][1]));
                m1 = fmaxf(m1, fmaxf(acc[mi][nt][2], acc[mi][nt][3]));
            }
            m0 = fmaxf(m0, __shfl_xor_sync(0xffffffffu, m0, 1));
            m0 = fmaxf(m0, __shfl_xor_sync(0xffffffffu, m0, 2));
            m1 = fmaxf(m1, __shfl_xor_sync(0xffffffffu, m1, 1));
            m1 = fmaxf(m1, __shfl_xor_sync(0xffffffffu, m1, 2));
            if ((lane & 3) == 0) {
                float* o = g_hmax + ((size_t)combo * Mn + mbase + nh) * 128 +
                           mt * 32 + mi * 16 + grp;
                o[0] = fmaxf(m0, 0.f);
                o[8] = fmaxf(m1, 0.f);
            }
        }
        __syncthreads();
    }
}

// ---------------------------------------------------------------------------
// K4: wt on tensor cores (unchanged)
// ---------------------------------------------------------------------------
__device__ __forceinline__ void wt_produce(char* bh, char* bl, const float4* pf,
                                           int col, int kq) {
#pragma unroll
    for (int q = 0; q < 4; q++) {
        float4 v = pf[q];
        __nv_bfloat162 hiA, hiB, loA, loB;
        hiA.x = __float2bfloat16_rn(v.x); hiA.y = __float2bfloat16_rn(v.y);
        hiB.x = __float2bfloat16_rn(v.z); hiB.y = __float2bfloat16_rn(v.w);
        loA.x = __float2bfloat16_rn(v.x - __bfloat162float(hiA.x));
        loA.y = __float2bfloat16_rn(v.y - __bfloat162float(hiA.y));
        loB.x = __float2bfloat16_rn(v.z - __bfloat162float(hiB.x));
        loB.y = __float2bfloat16_rn(v.w - __bfloat162float(hiB.y));
        int k0 = kq * 16 + q * 4;
        int chunk = k0 >> 3;
        int off = col * 256 + ((chunk ^ (col & 7)) << 4) + ((k0 & 7) << 1);
        uint2 vh, vl;
        vh.x = *(unsigned*)&hiA; vh.y = *(unsigned*)&hiB;
        vl.x = *(unsigned*)&loA; vl.y = *(unsigned*)&loB;
        *(uint2*)(bh + off) = vh;
        *(uint2*)(bl + off) = vl;
    }
}

__global__ void __launch_bounds__(256) wt_kernel(float* __restrict__ outf) {
    __shared__ __align__(16) __nv_bfloat16 Bh[2][32 * 128];
    __shared__ __align__(16) __nv_bfloat16 Bl[2][32 * 128];

    int t = threadIdx.x;
    int lane = t & 31, w = t >> 5;
    int bs = blockIdx.y;
    int mbase = blockIdx.x * 32;

    int col = t >> 3;
    int kq = t & 7;
    int brow_base = (lane & 7) + ((lane & 16) >> 1);
    int bksel = (lane >> 3) & 1;

    unsigned sBh0 = (unsigned)__cvta_generic_to_shared(Bh[0]);
    unsigned sBl0 = (unsigned)__cvta_generic_to_shared(Bl[0]);

    float4 pf[4];
    {
        const float4* src = (const float4*)(g_hmax +
            (((size_t)(bs * 3 + 0)) * Mn + mbase + col) * 128 + kq * 16);
#pragma unroll
        for (int q = 0; q < 4; q++) pf[q] = src[q];
    }
    wt_produce((char*)Bh[0], (char*)Bl[0], pf, col, kq);
    __syncthreads();

    float tot[2][4][4];
#pragma unroll
    for (int mt = 0; mt < 2; mt++)
#pragma unroll
        for (int nt = 0; nt < 4; nt++)
#pragma unroll
            for (int i = 0; i < 4; i++) tot[mt][nt][i] = 0.f;

    const uint4* fragHi = (const uint4*)g_WtFragHi;
    const uint4* fragLo = (const uint4*)g_WtFragLo;

#pragma unroll
    for (int j = 0; j < 3; j++) {
        if (j < 2) {
            const float4* src = (const float4*)(g_hmax +
                (((size_t)(bs * 3 + j + 1)) * Mn + mbase + col) * 128 + kq * 16);
#pragma unroll
            for (int q = 0; q < 4; q++) pf[q] = src[q];
        }

        float acc[2][4][4];
#pragma unroll
        for (int mt = 0; mt < 2; mt++)
#pragma unroll
            for (int nt = 0; nt < 4; nt++)
#pragma unroll
                for (int i = 0; i < 4; i++) acc[mt][nt][i] = 0.f;

        unsigned sBhj = sBh0 + (j & 1) * 8192;
        unsigned sBlj = sBl0 + (j & 1) * 8192;

#pragma unroll
        for (int ks = 0; ks < 8; ks++) {
            uint4 fh0 = fragHi[((j * 16 + w * 2 + 0) * 8 + ks) * 32 + lane];
            uint4 fl0 = fragLo[((j * 16 + w * 2 + 0) * 8 + ks) * 32 + lane];
            uint4 fh1 = fragHi[((j * 16 + w * 2 + 1) * 8 + ks) * 32 + lane];
            uint4 fl1 = fragLo[((j * 16 + w * 2 + 1) * 8 + ks) * 32 + lane];
            unsigned ah0[4] = {fh0.x, fh0.y, fh0.z, fh0.w};
            unsigned al0[4] = {fl0.x, fl0.y, fl0.z, fl0.w};
            unsigned ah1[4] = {fh1.x, fh1.y, fh1.z, fh1.w};
            unsigned al1[4] = {fl1.x, fl1.y, fl1.z, fl1.w};
            int chunk = ks * 2 + bksel;
#pragma unroll
            for (int p = 0; p < 2; p++) {
                int r = p * 16 + brow_base;
                unsigned off = r * 256 + ((chunk ^ (r & 7)) << 4);
                unsigned hh[4], ll[4];
                ldsm4(hh, sBhj + off);
                ldsm4(ll, sBlj + off);
                mma_bf16(acc[0][2 * p],     ah0, hh[0], hh[1]);
                mma_bf16(acc[0][2 * p],     ah0, ll[0], ll[1]);
                mma_bf16(acc[0][2 * p],     al0, hh[0], hh[1]);
                mma_bf16(acc[0][2 * p + 1], ah0, hh[2], hh[3]);
                mma_bf16(acc[0][2 * p + 1], ah0, ll[2], ll[3]);
                mma_bf16(acc[0][2 * p + 1], al0, hh[2], hh[3]);
                mma_bf16(acc[1][2 * p],     ah1, hh[0], hh[1]);
                mma_bf16(acc[1][2 * p],     ah1, ll[0], ll[1]);
                mma_bf16(acc[1][2 * p],     al1, hh[0], hh[1]);
                mma_bf16(acc[1][2 * p + 1], ah1, hh[2], hh[3]);
                mma_bf16(acc[1][2 * p + 1], ah1, ll[2], ll[3]);
                mma_bf16(acc[1][2 * p + 1], al1, hh[2], hh[3]);
            }
        }

        if (j < 2)
            wt_produce((char*)Bh[(j + 1) & 1], (char*)Bl[(j + 1) & 1], pf, col, kq);

#pragma unroll
        for (int mt = 0; mt < 2; mt++)
#pragma unroll
            for (int nt = 0; nt < 4; nt++)
#pragma unroll
                for (int i = 0; i < 4; i++)
                    tot[mt][nt][i] += fmaxf(acc[mt][nt][i], 0.f);
        __syncthreads();
    }

#pragma unroll
    for (int mt = 0; mt < 2; mt++) {
        int row = w * 32 + mt * 16 + (lane >> 2);
#pragma unroll
        for (int nt = 0; nt < 4; nt++) {
            int c = mbase + nt * 8 + (lane & 3) * 2;
            float2 v0; v0.x = tot[mt][nt][0]; v0.y = tot[mt][nt][1];
            float2 v1; v1.x = tot[mt][nt][2]; v1.y = tot[mt][nt][3];
            *(float2*)&outf[((size_t)bs * 256 + row) * Mn + c] = v0;
            *(float2*)&outf[((size_t)bs * 256 + row + 8) * Mn + c] = v1;
        }
    }
}

// ---------------------------------------------------------------------------
extern "C" void kernel_launch(void* const* d_in, const int* in_sizes, int n_in,
                              void* d_out, int out_size) {
    const float* xyzs = (const float*)d_in[0];
    const float* feats = (const float*)d_in[1];
    const float* Ws0 = (const float*)d_in[2];
    const float* Ws1 = (const float*)d_in[3];
    const float* Wt = (const float*)d_in[4];
    float* out = (float*)d_out;

    const int XYZ_TOTAL = Bn * Sn * Mn * 3;  // 196608

    fps_prep_kernel<<<960, 256>>>(xyzs, out, feats, Ws0, Ws1, Wt);        // 1
    ball_query_A_kernel<<<dim3(Mn / 8, 97), 256>>>(xyzs, Ws0);            // 2
    mlp_kernel<<<dim3(Mn * Kn / (64 * MLP_REPS), Bn * Sn * Jn), 256>>>(); // 3
    wt_kernel<<<dim3(Mn / 32, Bn * Sn), 256>>>(out + XYZ_TOTAL);          // 4 (profiled)
}

// round 13
// speedup vs baseline: 1.0188x; 1.0188x over previous
#include <cuda_runtime.h>
#include <cuda_bf16.h>

// Problem constants
#define Bn 4
#define Ln 8
#define Nn 4096
#define Mn 2048
#define Kn 32
#define Sn 8
#define Jn 3

// Staging buffers (device globals; no runtime allocation)
__device__ float g_anchors[Bn * Sn * Mn * 3];
__device__ float g_P[Bn * 8 * Nn * 64];
__device__ float g_A[Bn * Sn * Mn * 64];
__device__ int   g_idx[Bn * Sn * Jn * Mn * Kn];
__device__ float g_hmax[Bn * Sn * Jn * Mn * 128];        // [combo][m][r]
__device__ __nv_bfloat16 g_Ws1hi[128 * 64];              // Ws1 hi, [r][k] row-major
__device__ unsigned g_WsFragLo[8 * 4 * 32 * 4];          // Ws1 lo in mma A-frag layout
__device__ unsigned g_WtFragHi[3 * 16 * 8 * 32 * 4];     // Wt hi in mma A-frag layout
__device__ unsigned g_WtFragLo[3 * 16 * 8 * 32 * 4];     // Wt lo

// ---------------------------------------------------------------------------
// packed f32x2 helpers (per-lane IEEE rn — identical to __fadd_rn/__fmul_rn)
// ---------------------------------------------------------------------------
__device__ __forceinline__ unsigned long long f2pack(float lo, float hi) {
    unsigned long long r;
    asm("mov.b64 %0, {%1, %2};" : "=l"(r) : "f"(lo), "f"(hi));
    return r;
}
__device__ __forceinline__ void f2unpack(float& lo, float& hi, unsigned long long v) {
    asm("mov.b64 {%0, %1}, %2;" : "=f"(lo), "=f"(hi) : "l"(v));
}
__device__ __forceinline__ unsigned long long f2add(unsigned long long a,
                                                    unsigned long long b) {
    unsigned long long r;
    asm("add.rn.f32x2 %0, %1, %2;" : "=l"(r) : "l"(a), "l"(b));
    return r;
}
__device__ __forceinline__ unsigned long long f2mul(unsigned long long a,
                                                    unsigned long long b) {
    unsigned long long r;
    asm("mul.rn.f32x2 %0, %1, %2;" : "=l"(r) : "l"(a), "l"(b));
    return r;
}

// ---------------------------------------------------------------------------
// K1 (merged): blocks 0-31: FPS (R11 version). blocks 32-543: P projection.
// blocks 544-735: wtfrag hi. blocks 736-927: wtfrag lo. blocks 928-959: Ws1.
// All non-fps work is fps-independent and rides in fps's shadow.
// ---------------------------------------------------------------------------
__global__ void __launch_bounds__(256) fps_prep_kernel(
    const float* __restrict__ xyzs, float* __restrict__ out_xyz,
    const float* __restrict__ feats, const float* __restrict__ Ws0,
    const float* __restrict__ Ws1, const float* __restrict__ Wt) {
    int t = threadIdx.x;
    int blk = blockIdx.x;

    if (blk < 32) {
        // ---------------- FPS ----------------
        int bs = blk;
        const float* xyz = xyzs + (size_t)bs * Nn * 3;
        __shared__ unsigned long long skey[2][8];

        int lane = t & 31, wid = t >> 5;

        unsigned long long pxx[8], pyy[8], pzz[8];
        float pd[16];
#pragma unroll
        for (int i = 0; i < 8; i++) {
            int p0 = t + (2 * i) * 256;
            int p1 = t + (2 * i + 1) * 256;
            pxx[i] = f2pack(xyz[3 * p0], xyz[3 * p1]);
            pyy[i] = f2pack(xyz[3 * p0 + 1], xyz[3 * p1 + 1]);
            pzz[i] = f2pack(xyz[3 * p0 + 2], xyz[3 * p1 + 2]);
            pd[2 * i] = 1e10f;
            pd[2 * i + 1] = 1e10f;
        }
        float cx = xyz[0], cy = xyz[1], cz = xyz[2];

        float* oanc = g_anchors + (size_t)bs * Mn * 3;
        float* oxyz = out_xyz + (size_t)bs * Mn * 3;

        for (int m = 0; m < Mn; m++) {
            if (t == 0) {
                oanc[3 * m] = cx; oanc[3 * m + 1] = cy; oanc[3 * m + 2] = cz;
                oxyz[3 * m] = cx; oxyz[3 * m + 1] = cy; oxyz[3 * m + 2] = cz;
            }
            unsigned long long vcx = f2pack(-cx, -cx);
            unsigned long long vcy = f2pack(-cy, -cy);
            unsigned long long vcz = f2pack(-cz, -cz);
            unsigned long long key = 0;
#pragma unroll
            for (int i = 0; i < 8; i++) {
                unsigned long long dx = f2add(pxx[i], vcx);
                unsigned long long dy = f2add(pyy[i], vcy);
                unsigned long long dz = f2add(pzz[i], vcz);
                unsigned long long ssum =
                    f2add(f2add(f2mul(dx, dx), f2mul(dy, dy)), f2mul(dz, dz));
                float d0, d1;
                f2unpack(d0, d1, ssum);
                float nd0 = fminf(pd[2 * i], d0);
                float nd1 = fminf(pd[2 * i + 1], d1);
                pd[2 * i] = nd0;
                pd[2 * i + 1] = nd1;
                unsigned long long k0 =
                    ((unsigned long long)__float_as_uint(nd0) << 32) |
                    (unsigned)(0xFFFFFFFFu - (unsigned)(t + (2 * i) * 256));
                unsigned long long k1 =
                    ((unsigned long long)__float_as_uint(nd1) << 32) |
                    (unsigned)(0xFFFFFFFFu - (unsigned)(t + (2 * i + 1) * 256));
                key = (k0 > key) ? k0 : key;
                key = (k1 > key) ? k1 : key;
            }
#pragma unroll
            for (int off = 16; off > 0; off >>= 1) {
                unsigned long long k2 = __shfl_xor_sync(0xffffffffu, key, off);
                key = (k2 > key) ? k2 : key;
            }
            if (lane == 0) skey[m & 1][wid] = key;
            __syncthreads();
            unsigned long long kb = skey[m & 1][0];
#pragma unroll
            for (int wq = 1; wq < 8; wq++) {
                unsigned long long k2 = skey[m & 1][wq];
                kb = (k2 > kb) ? k2 : kb;
            }
            int widx = (int)(0xFFFFFFFFu - (unsigned)kb);
            cx = xyz[3 * widx]; cy = xyz[3 * widx + 1]; cz = xyz[3 * widx + 2];
        }
    } else if (blk < 544) {
        // ---------------- P projection ----------------
        __shared__ float w[64 * 6];
        for (int i = t; i < 64 * 6; i += 256) w[i] = Ws0[i];
        __syncthreads();

        int gp = (blk - 32) * 256 + t;
        int n = gp & (Nn - 1);
        int bf = gp >> 12;
        const float* p = xyzs + (size_t)gp * 3;
        float x = p[0], y = p[1], z = p[2];
        const float* f = feats + (size_t)bf * 3 * Nn + n;
        float f0 = f[0], f1 = f[Nn], f2 = f[2 * Nn];
        float4* o = (float4*)(g_P + (size_t)gp * 64);
#pragma unroll
        for (int oo = 0; oo < 64; oo += 4) {
            float4 r;
            const float* w0 = w + oo * 6;
            r.x = w0[0] * x + w0[1] * y + w0[2] * z + w0[3] * f0 + w0[4] * f1 + w0[5] * f2;
            r.y = w0[6] * x + w0[7] * y + w0[8] * z + w0[9] * f0 + w0[10] * f1 + w0[11] * f2;
            r.z = w0[12] * x + w0[13] * y + w0[14] * z + w0[15] * f0 + w0[16] * f1 + w0[17] * f2;
            r.w = w0[18] * x + w0[19] * y + w0[20] * z + w0[21] * f0 + w0[22] * f1 + w0[23] * f2;
            o[oo >> 2] = r;
        }
    } else if (blk < 736) {
        // ---------------- wtfrag hi ----------------
        int i = (blk - 544) * 256 + t;
        int q = i & 3, lane = (i >> 2) & 31, ks = (i >> 7) & 7, rb = (i >> 10) & 15, j = i >> 14;
        int row = rb * 16 + (lane >> 2) + (q & 1) * 8;
        int k = ks * 16 + (lane & 3) * 2 + ((q >> 1) & 1) * 8;
        float e0 = Wt[(j * 256 + row) * 128 + k];
        float e1 = Wt[(j * 256 + row) * 128 + k + 1];
        __nv_bfloat16 h0 = __float2bfloat16_rn(e0);
        __nv_bfloat16 h1 = __float2bfloat16_rn(e1);
        unsigned u0 = *(unsigned short*)&h0, u1 = *(unsigned short*)&h1;
        g_WtFragHi[i] = (u1 << 16) | u0;
    } else if (blk < 928) {
        // ---------------- wtfrag lo ----------------
        int i = (blk - 736) * 256 + t;
        int q = i & 3, lane = (i >> 2) & 31, ks = (i >> 7) & 7, rb = (i >> 10) & 15, j = i >> 14;
        int row = rb * 16 + (lane >> 2) + (q & 1) * 8;
        int k = ks * 16 + (lane & 3) * 2 + ((q >> 1) & 1) * 8;
        float e0 = Wt[(j * 256 + row) * 128 + k];
        float e1 = Wt[(j * 256 + row) * 128 + k + 1];
        __nv_bfloat16 h0 = __float2bfloat16_rn(e0);
        __nv_bfloat16 h1 = __float2bfloat16_rn(e1);
        __nv_bfloat16 l0 = __float2bfloat16_rn(e0 - __bfloat162float(h0));
        __nv_bfloat16 l1 = __float2bfloat16_rn(e1 - __bfloat162float(h1));
        unsigned u0 = *(unsigned short*)&l0, u1 = *(unsigned short*)&l1;
        g_WtFragLo[i] = (u1 << 16) | u0;
    } else {
        // ---------------- Ws1 prep ----------------
        int i = (blk - 928) * 256 + t;  // < 8192
        if (i < 128 * 64) {
            g_Ws1hi[i] = __float2bfloat16_rn(Ws1[i]);
        }
        if (i < 8 * 4 * 32 * 4) {
            int q = i & 3, lane = (i >> 2) & 31, ks = (i >> 7) & 3, w8 = i >> 9;
            int row = w8 * 16 + (lane >> 2) + (q & 1) * 8;
            int k = ks * 16 + (lane & 3) * 2 + ((q >> 1) & 1) * 8;
            float e0 = Ws1[row * 64 + k];
            float e1 = Ws1[row * 64 + k + 1];
            __nv_bfloat16 h0 = __float2bfloat16_rn(e0);
            __nv_bfloat16 h1 = __float2bfloat16_rn(e1);
            __nv_bfloat16 l0 = __float2bfloat16_rn(e0 - __bfloat162float(h0));
            __nv_bfloat16 l1 = __float2bfloat16_rn(e1 - __bfloat162float(h1));
            unsigned ul0 = *(unsigned short*)&l0, ul1 = *(unsigned short*)&l1;
            g_WsFragLo[i] = (ul1 << 16) | ul0;
        }
    }
}

// ---------------------------------------------------------------------------
// K2 (merged): blockIdx.y < 96: ball query — R11's SCALAR float4 version
// (known good). blockIdx.y == 96: A projection.
// ---------------------------------------------------------------------------
__global__ void __launch_bounds__(256) ball_query_A_kernel(
    const float* __restrict__ xyzs, const float* __restrict__ Ws0) {
    int t = threadIdx.x;
    if (blockIdx.y == 96) {
        // ---------------- A projection ----------------
        __shared__ float w[64 * 3];
        for (int i = t; i < 64 * 3; i += 256) {
            int o = i / 3, c = i % 3;
            w[i] = Ws0[o * 6 + c];
        }
        __syncthreads();
        int ga = blockIdx.x * 256 + t;  // 0..65535
        const float* a = g_anchors + (size_t)ga * 3;
        float x = a[0], y = a[1], z = a[2];
        float4* o = (float4*)(g_A + (size_t)ga * 64);
#pragma unroll
        for (int oo = 0; oo < 64; oo += 4) {
            float4 r;
            const float* w0 = w + oo * 3;
            r.x = w0[0] * x + w0[1] * y + w0[2] * z;
            r.y = w0[3] * x + w0[4] * y + w0[5] * z;
            r.z = w0[6] * x + w0[7] * y + w0[8] * z;
            r.w = w0[9] * x + w0[10] * y + w0[11] * z;
            o[oo >> 2] = r;
        }
        return;
    }

    // ---------------- ball query (R11 scalar math) ----------------
    int combo = blockIdx.y;
    int j = combo % 3;
    int bs = combo / 3;
    int b = bs >> 3, s = bs & 7;
    int g = s - 1 + j;
    g = g < 0 ? 0 : (g > 7 ? 7 : g);
    int wid = t >> 5, lane = t & 31;
    int m = blockIdx.x * 8 + wid;

    const float* pts = xyzs + (size_t)(b * 8 + g) * Nn * 3;
    const float* anc = g_anchors + ((size_t)bs * Mn + m) * 3;
    float ax = anc[0], ay = anc[1], az = anc[2];
    int* out = g_idx + ((size_t)combo * Mn + m) * Kn;

    int found = 0, first = -1;
    unsigned lt = (1u << lane) - 1u;
    for (int base = 0; base < Nn && found < Kn; base += 128) {
        int n0 = base + 4 * lane;
        const float4* pp = (const float4*)(pts + 3 * n0);
        float4 v0 = pp[0];
        float4 v1 = pp[1];
        float4 v2 = pp[2];

        float dx, dy, dz;
        dx = __fsub_rn(v0.x, ax); dy = __fsub_rn(v0.y, ay); dz = __fsub_rn(v0.z, az);
        float d0 = __fadd_rn(__fadd_rn(__fmul_rn(dx, dx), __fmul_rn(dy, dy)), __fmul_rn(dz, dz));
        dx = __fsub_rn(v0.w, ax); dy = __fsub_rn(v1.x, ay); dz = __fsub_rn(v1.y, az);
        float d1 = __fadd_rn(__fadd_rn(__fmul_rn(dx, dx), __fmul_rn(dy, dy)), __fmul_rn(dz, dz));
        dx = __fsub_rn(v1.z, ax); dy = __fsub_rn(v1.w, ay); dz = __fsub_rn(v2.x, az);
        float d2 = __fadd_rn(__fadd_rn(__fmul_rn(dx, dx), __fmul_rn(dy, dy)), __fmul_rn(dz, dz));
        dx = __fsub_rn(v2.y, ax); dy = __fsub_rn(v2.z, ay); dz = __fsub_rn(v2.w, az);
        float d3 = __fadd_rn(__fadd_rn(__fmul_rn(dx, dx), __fmul_rn(dy, dy)), __fmul_rn(dz, dz));

        bool p0 = d0 < 0.25f, p1 = d1 < 0.25f, p2 = d2 < 0.25f, p3 = d3 < 0.25f;
        unsigned m0 = __ballot_sync(0xffffffffu, p0);
        unsigned m1 = __ballot_sync(0xffffffffu, p1);
        unsigned m2 = __ballot_sync(0xffffffffu, p2);
        unsigned m3 = __ballot_sync(0xffffffffu, p3);

        if (first < 0 && (m0 | m1 | m2 | m3)) {
            int c0 = m0 ? 4 * (__ffs(m0) - 1) + 0 : 0x7fffffff;
            int c1 = m1 ? 4 * (__ffs(m1) - 1) + 1 : 0x7fffffff;
            int c2 = m2 ? 4 * (__ffs(m2) - 1) + 2 : 0x7fffffff;
            int c3 = m3 ? 4 * (__ffs(m3) - 1) + 3 : 0x7fffffff;
            int cmin = c0 < c1 ? c0 : c1;
            cmin = c2 < cmin ? c2 : cmin;
            cmin = c3 < cmin ? c3 : cmin;
            first = base + cmin;
        }
        int pos = found + __popc(m0 & lt) + __popc(m1 & lt) +
                  __popc(m2 & lt) + __popc(m3 & lt);
        if (p0 && pos < Kn) out[pos] = n0;
        pos += p0 ? 1 : 0;
        if (p1 && pos < Kn) out[pos] = n0 + 1;
        pos += p1 ? 1 : 0;
        if (p2 && pos < Kn) out[pos] = n0 + 2;
        pos += p2 ? 1 : 0;
        if (p3 && pos < Kn) out[pos] = n0 + 3;
        found += __popc(m0) + __popc(m1) + __popc(m2) + __popc(m3);
    }
    if (found < Kn) {
        int pad = first < 0 ? 0 : first;
        for (int p = found + lane; p < Kn; p += 32) out[p] = pad;
    }
}

// ---------------------------------------------------------------------------
// mma / ldsm helpers
// ---------------------------------------------------------------------------
__device__ __forceinline__ void mma_bf16(float c[4], const unsigned a[4],
                                         unsigned b0, unsigned b1) {
    asm volatile(
        "mma.sync.aligned.m16n8k16.row.col.f32.bf16.bf16.f32 "
        "{%0,%1,%2,%3}, {%4,%5,%6,%7}, {%8,%9}, {%0,%1,%2,%3};"
        : "+f"(c[0]), "+f"(c[1]), "+f"(c[2]), "+f"(c[3])
        : "r"(a[0]), "r"(a[1]), "r"(a[2]), "r"(a[3]), "r"(b0), "r"(b1));
}

__device__ __forceinline__ void ldsm4(unsigned r[4], unsigned saddr) {
    asm volatile(
        "ldmatrix.sync.aligned.m8n8.x4.shared.b16 {%0,%1,%2,%3}, [%4];"
        : "=r"(r[0]), "=r"(r[1]), "=r"(r[2]), "=r"(r[3])
        : "r"(saddr));
}

// ---------------------------------------------------------------------------
// K3: mlp (R11 exact — 32x32 warp tile, REPS=8)
// ---------------------------------------------------------------------------
#define MLP_REPS 8

__global__ void __launch_bounds__(256, 2) mlp_kernel() {
    __shared__ __align__(16) __nv_bfloat16 Whi[128 * 64];
    __shared__ __align__(16) __nv_bfloat16 Bhs[2][64 * 64];
    __shared__ __align__(16) __nv_bfloat16 Bls[2][64 * 64];

    int t = threadIdx.x;
    int lane = t & 31, w = t >> 5;
    int mt = w >> 1;
    int nh = w & 1;
    int combo = blockIdx.y;
    int j = combo % 3;
    int bs = combo / 3;
    int b = bs >> 3, s = bs & 7;
    int g = s - 1 + j;
    g = g < 0 ? 0 : (g > 7 ? 7 : g);

    {
        const uint4* gh = (const uint4*)g_Ws1hi;
        uint4* sh = (uint4*)Whi;
        for (int i = t; i < 1024; i += 256) {
            int r = i >> 3, c = i & 7;
            sh[(r << 3) + (c ^ (r & 7))] = gh[i];
        }
    }
    __syncthreads();

    unsigned sWhi = (unsigned)__cvta_generic_to_shared(Whi);
    unsigned sBh0 = (unsigned)__cvta_generic_to_shared(Bhs[0]);
    unsigned sBl0 = (unsigned)__cvta_generic_to_shared(Bls[0]);

    unsigned ahi[2][4][4];
#pragma unroll
    for (int mi = 0; mi < 2; mi++) {
        int r = mt * 32 + mi * 16 + (lane & 15);
#pragma unroll
        for (int ks = 0; ks < 4; ks++) {
            int chunk = ks * 2 + (lane >> 4);
            ldsm4(ahi[mi][ks], sWhi + r * 128 + ((chunk ^ (r & 7)) << 4));
        }
    }

    int col = t & 63;
    int kq = t >> 6;
    int brow_base = (lane & 7) + ((lane & 16) >> 1);
    int bksel = (lane >> 3) & 1;

    const float4* Pbase = (const float4*)(g_P + (size_t)(b * 8 + g) * Nn * 64);
    const float4* Abase = (const float4*)(g_A + (size_t)bs * Mn * 64);
    const int* idxbase = g_idx + (size_t)combo * Mn * Kn;
    const uint4* fragLoV = (const uint4*)g_WsFragLo;

    float4 pf_p[4];
    int mcur;

    {
        int gcol = blockIdx.x * MLP_REPS * 64 + col;
        mcur = gcol >> 5;
        int knb = gcol & 31;
        int n = idxbase[mcur * Kn + knb];
        const float4* Prow = Pbase + (size_t)n * 16;
#pragma unroll
        for (int q = 0; q < 4; q++) pf_p[q] = Prow[kq * 4 + q];
    }
    {
        const float4* Arow = Abase + (size_t)mcur * 16;
        char* bh = (char*)Bhs[0];
        char* bl = (char*)Bls[0];
#pragma unroll
        for (int q = 0; q < 4; q++) {
            float4 a4 = Arow[kq * 4 + q];
            float h0 = fmaxf(pf_p[q].x - a4.x, 0.f);
            float h1 = fmaxf(pf_p[q].y - a4.y, 0.f);
            float h2 = fmaxf(pf_p[q].z - a4.z, 0.f);
            float h3 = fmaxf(pf_p[q].w - a4.w, 0.f);
            __nv_bfloat162 hiA, hiB, loA, loB;
            hiA.x = __float2bfloat16_rn(h0); hiA.y = __float2bfloat16_rn(h1);
            hiB.x = __float2bfloat16_rn(h2); hiB.y = __float2bfloat16_rn(h3);
            loA.x = __float2bfloat16_rn(h0 - __bfloat162float(hiA.x));
            loA.y = __float2bfloat16_rn(h1 - __bfloat162float(hiA.y));
            loB.x = __float2bfloat16_rn(h2 - __bfloat162float(hiB.x));
            loB.y = __float2bfloat16_rn(h3 - __bfloat162float(hiB.y));
            int k0 = kq * 16 + q * 4;
            int chunk = k0 >> 3;
            int off = col * 128 + ((chunk ^ (col & 7)) << 4) + ((k0 & 7) << 1);
            uint2 vh, vl;
            vh.x = *(unsigned*)&hiA; vh.y = *(unsigned*)&hiB;
            vl.x = *(unsigned*)&loA; vl.y = *(unsigned*)&loB;
            *(uint2*)(bh + off) = vh;
            *(uint2*)(bl + off) = vl;
        }
    }
    __syncthreads();

    for (int rep = 0; rep < MLP_REPS; rep++) {
        int buf = rep & 1;
        int mnext = mcur;
        if (rep + 1 < MLP_REPS) {
            int gcol = (blockIdx.x * MLP_REPS + rep + 1) * 64 + col;
            mnext = gcol >> 5;
            int knb = gcol & 31;
            int n = idxbase[mnext * Kn + knb];
            const float4* Prow = Pbase + (size_t)n * 16;
#pragma unroll
            for (int q = 0; q < 4; q++) pf_p[q] = Prow[kq * 4 + q];
        }

        float acc[2][4][4];
#pragma unroll
        for (int mi = 0; mi < 2; mi++)
#pragma unroll
            for (int nt = 0; nt < 4; nt++)
#pragma unroll
                for (int i = 0; i < 4; i++) acc[mi][nt][i] = 0.f;

        unsigned sBh = sBh0 + buf * 8192;
        unsigned sBl = sBl0 + buf * 8192;
#pragma unroll
        for (int ks = 0; ks < 4; ks++) {
            uint4 fl0 = fragLoV[((mt * 2 + 0) * 4 + ks) * 32 + lane];
            uint4 fl1 = fragLoV[((mt * 2 + 1) * 4 + ks) * 32 + lane];
            unsigned alo0[4] = {fl0.x, fl0.y, fl0.z, fl0.w};
            unsigned alo1[4] = {fl1.x, fl1.y, fl1.z, fl1.w};
            int chunk = ks * 2 + bksel;
#pragma unroll
            for (int p = 0; p < 2; p++) {
                int r = nh * 32 + p * 16 + brow_base;
                unsigned off = r * 128 + ((chunk ^ (r & 7)) << 4);
                unsigned hh[4], ll[4];
                ldsm4(hh, sBh + off);
                ldsm4(ll, sBl + off);
                mma_bf16(acc[0][2 * p],     ahi[0][ks], hh[0], hh[1]);
                mma_bf16(acc[0][2 * p + 1], ahi[0][ks], hh[2], hh[3]);
                mma_bf16(acc[1][2 * p],     ahi[1][ks], hh[0], hh[1]);
                mma_bf16(acc[1][2 * p + 1], ahi[1][ks], hh[2], hh[3]);
                mma_bf16(acc[0][2 * p],     ahi[0][ks], ll[0], ll[1]);
                mma_bf16(acc[0][2 * p + 1], ahi[0][ks], ll[2], ll[3]);
                mma_bf16(acc[1][2 * p],     ahi[1][ks], ll[0], ll[1]);
                mma_bf16(acc[1][2 * p + 1], ahi[1][ks], ll[2], ll[3]);
                mma_bf16(acc[0][2 * p],     alo0,       hh[0], hh[1]);
                mma_bf16(acc[0][2 * p + 1], alo0,       hh[2], hh[3]);
                mma_bf16(acc[1][2 * p],     alo1,       hh[0], hh[1]);
                mma_bf16(acc[1][2 * p + 1], alo1,       hh[2], hh[3]);
            }
        }

        if (rep + 1 < MLP_REPS) {
            const float4* Arow = Abase + (size_t)mnext * 16;
            char* bh = (char*)Bhs[buf ^ 1];
            char* bl = (char*)Bls[buf ^ 1];
#pragma unroll
            for (int q = 0; q < 4; q++) {
                float4 a4 = Arow[kq * 4 + q];
                float h0 = fmaxf(pf_p[q].x - a4.x, 0.f);
                float h1 = fmaxf(pf_p[q].y - a4.y, 0.f);
                float h2 = fmaxf(pf_p[q].z - a4.z, 0.f);
                float h3 = fmaxf(pf_p[q].w - a4.w, 0.f);
                __nv_bfloat162 hiA, hiB, loA, loB;
                hiA.x = __float2bfloat16_rn(h0); hiA.y = __float2bfloat16_rn(h1);
                hiB.x = __float2bfloat16_rn(h2); hiB.y = __float2bfloat16_rn(h3);
                loA.x = __float2bfloat16_rn(h0 - __bfloat162float(hiA.x));
                loA.y = __float2bfloat16_rn(h1 - __bfloat162float(hiA.y));
                loB.x = __float2bfloat16_rn(h2 - __bfloat162float(hiB.x));
                loB.y = __float2bfloat16_rn(h3 - __bfloat162float(hiB.y));
                int k0 = kq * 16 + q * 4;
                int chunk = k0 >> 3;
                int off = col * 128 + ((chunk ^ (col & 7)) << 4) + ((k0 & 7) << 1);
                uint2 vh, vl;
                vh.x = *(unsigned*)&hiA; vh.y = *(unsigned*)&hiB;
                vl.x = *(unsigned*)&loA; vl.y = *(unsigned*)&loB;
                *(uint2*)(bh + off) = vh;
                *(uint2*)(bl + off) = vl;
            }
        }
        mcur = mnext;

        int mbase = (blockIdx.x * MLP_REPS + rep) * 2;
        int grp = lane >> 2;
#pragma unroll
        for (int mi = 0; mi < 2; mi++) {
            float m0 = -1e30f, m1 = -1e30f;
#pragma unroll
            for (int nt = 0; nt < 4; nt++) {
                m0 = fmaxf(m0, fmaxf(acc[mi][nt][0], acc[mi][nt][1]));
                m1 = fmaxf(m1, fmaxf(acc[mi][nt][2], acc[mi][nt][3]));
            }
            m0 = fmaxf(m0, __shfl_xor_sync(0xffffffffu, m0, 1));
            m0 = fmaxf(m0, __shfl_xor_sync(0xffffffffu, m0, 2));
            m1 = fmaxf(m1, __shfl_xor_sync(0xffffffffu, m1, 1));
            m1 = fmaxf(m1, __shfl_xor_sync(0xffffffffu, m1, 2));
            if ((lane & 3) == 0) {
                float* o = g_hmax + ((size_t)combo * Mn + mbase + nh) * 128 +
                           mt * 32 + mi * 16 + grp;
                o[0] = fmaxf(m0, 0.f);
                o[8] = fmaxf(m1, 0.f);
            }
        }
        __syncthreads();
    }
}

// ---------------------------------------------------------------------------
// K4: wt on tensor cores (unchanged)
// ---------------------------------------------------------------------------
__device__ __forceinline__ void wt_produce(char* bh, char* bl, const float4* pf,
                                           int col, int kq) {
#pragma unroll
    for (int q = 0; q < 4; q++) {
        float4 v = pf[q];
        __nv_bfloat162 hiA, hiB, loA, loB;
        hiA.x = __float2bfloat16_rn(v.x); hiA.y = __float2bfloat16_rn(v.y);
        hiB.x = __float2bfloat16_rn(v.z); hiB.y = __float2bfloat16_rn(v.w);
        loA.x = __float2bfloat16_rn(v.x - __bfloat162float(hiA.x));
        loA.y = __float2bfloat16_rn(v.y - __bfloat162float(hiA.y));
        loB.x = __float2bfloat16_rn(v.z - __bfloat162float(hiB.x));
        loB.y = __float2bfloat16_rn(v.w - __bfloat162float(hiB.y));
        int k0 = kq * 16 + q * 4;
        int chunk = k0 >> 3;
        int off = col * 256 + ((chunk ^ (col & 7)) << 4) + ((k0 & 7) << 1);
        uint2 vh, vl;
        vh.x = *(unsigned*)&hiA; vh.y = *(unsigned*)&hiB;
        vl.x = *(unsigned*)&loA; vl.y = *(unsigned*)&loB;
        *(uint2*)(bh + off) = vh;
        *(uint2*)(bl + off) = vl;
    }
}

__global__ void __launch_bounds__(256) wt_kernel(float* __restrict__ outf) {
    __shared__ __align__(16) __nv_bfloat16 Bh[2][32 * 128];
    __shared__ __align__(16) __nv_bfloat16 Bl[2][32 * 128];

    int t = threadIdx.x;
    int lane = t & 31, w = t >> 5;
    int bs = blockIdx.y;
    int mbase = blockIdx.x * 32;

    int col = t >> 3;
    int kq = t & 7;
    int brow_base = (lane & 7) + ((lane & 16) >> 1);
    int bksel = (lane >> 3) & 1;

    unsigned sBh0 = (unsigned)__cvta_generic_to_shared(Bh[0]);
    unsigned sBl0 = (unsigned)__cvta_generic_to_shared(Bl[0]);

    float4 pf[4];
    {
        const float4* src = (const float4*)(g_hmax +
            (((size_t)(bs * 3 + 0)) * Mn + mbase + col) * 128 + kq * 16);
#pragma unroll
        for (int q = 0; q < 4; q++) pf[q] = src[q];
    }
    wt_produce((char*)Bh[0], (char*)Bl[0], pf, col, kq);
    __syncthreads();

    float tot[2][4][4];
#pragma unroll
    for (int mt = 0; mt < 2; mt++)
#pragma unroll
        for (int nt = 0; nt < 4; nt++)
#pragma unroll
            for (int i = 0; i < 4; i++) tot[mt][nt][i] = 0.f;

    const uint4* fragHi = (const uint4*)g_WtFragHi;
    const uint4* fragLo = (const uint4*)g_WtFragLo;

#pragma unroll
    for (int j = 0; j < 3; j++) {
        if (j < 2) {
            const float4* src = (const float4*)(g_hmax +
                (((size_t)(bs * 3 + j + 1)) * Mn + mbase + col) * 128 + kq * 16);
#pragma unroll
            for (int q = 0; q < 4; q++) pf[q] = src[q];
        }

        float acc[2][4][4];
#pragma unroll
        for (int mt = 0; mt < 2; mt++)
#pragma unroll
            for (int nt = 0; nt < 4; nt++)
#pragma unroll
                for (int i = 0; i < 4; i++) acc[mt][nt][i] = 0.f;

        unsigned sBhj = sBh0 + (j & 1) * 8192;
        unsigned sBlj = sBl0 + (j & 1) * 8192;

#pragma unroll
        for (int ks = 0; ks < 8; ks++) {
            uint4 fh0 = fragHi[((j * 16 + w * 2 + 0) * 8 + ks) * 32 + lane];
            uint4 fl0 = fragLo[((j * 16 + w * 2 + 0) * 8 + ks) * 32 + lane];
            uint4 fh1 = fragHi[((j * 16 + w * 2 + 1) * 8 + ks) * 32 + lane];
            uint4 fl1 = fragLo[((j * 16 + w * 2 + 1) * 8 + ks) * 32 + lane];
            unsigned ah0[4] = {fh0.x, fh0.y, fh0.z, fh0.w};
            unsigned al0[4] = {fl0.x, fl0.y, fl0.z, fl0.w};
            unsigned ah1[4] = {fh1.x, fh1.y, fh1.z, fh1.w};
            unsigned al1[4] = {fl1.x, fl1.y, fl1.z, fl1.w};
            int chunk = ks * 2 + bksel;
#pragma unroll
            for (int p = 0; p < 2; p++) {
                int r = p * 16 + brow_base;
                unsigned off = r * 256 + ((chunk ^ (r & 7)) << 4);
                unsigned hh[4], ll[4];
                ldsm4(hh, sBhj + off);
                ldsm4(ll, sBlj + off);
                mma_bf16(acc[0][2 * p],     ah0, hh[0], hh[1]);
                mma_bf16(acc[0][2 * p],     ah0, ll[0], ll[1]);
                mma_bf16(acc[0][2 * p],     al0, hh[0], hh[1]);
                mma_bf16(acc[0][2 * p + 1], ah0, hh[2], hh[3]);
                mma_bf16(acc[0][2 * p + 1], ah0, ll[2], ll[3]);
                mma_bf16(acc[0][2 * p + 1], al0, hh[2], hh[3]);
                mma_bf16(acc[1][2 * p],     ah1, hh[0], hh[1]);
                mma_bf16(acc[1][2 * p],     ah1, ll[0], ll[1]);
                mma_bf16(acc[1][2 * p],     al1, hh[0], hh[1]);
                mma_bf16(acc[1][2 * p + 1], ah1, hh[2], hh[3]);
                mma_bf16(acc[1][2 * p + 1], ah1, ll[2], ll[3]);
                mma_bf16(acc[1][2 * p + 1], al1, hh[2], hh[3]);
            }
        }

        if (j < 2)
            wt_produce((char*)Bh[(j + 1) & 1], (char*)Bl[(j + 1) & 1], pf, col, kq);

#pragma unroll
        for (int mt = 0; mt < 2; mt++)
#pragma unroll
            for (int nt = 0; nt < 4; nt++)
#pragma unroll
                for (int i = 0; i < 4; i++)
                    tot[mt][nt][i] += fmaxf(acc[mt][nt][i], 0.f);
        __syncthreads();
    }

#pragma unroll
    for (int mt = 0; mt < 2; mt++) {
        int row = w * 32 + mt * 16 + (lane >> 2);
#pragma unroll
        for (int nt = 0; nt < 4; nt++) {
            int c = mbase + nt * 8 + (lane & 3) * 2;
            float2 v0; v0.x = tot[mt][nt][0]; v0.y = tot[mt][nt][1];
            float2 v1; v1.x = tot[mt][nt][2]; v1.y = tot[mt][nt][3];
            *(float2*)&outf[((size_t)bs * 256 + row) * Mn + c] = v0;
            *(float2*)&outf[((size_t)bs * 256 + row + 8) * Mn + c] = v1;
        }
    }
}

// ---------------------------------------------------------------------------
extern "C" void kernel_launch(void* const* d_in, const int* in_sizes, int n_in,
                              void* d_out, int out_size) {
    const float* xyzs = (const float*)d_in[0];
    const float* feats = (const float*)d_in[1];
    const float* Ws0 = (const float*)d_in[2];
    const float* Ws1 = (const float*)d_in[3];
    const float* Wt = (const float*)d_in[4];
    float* out = (float*)d_out;

    const int XYZ_TOTAL = Bn * Sn * Mn * 3;  // 196608

    fps_prep_kernel<<<960, 256>>>(xyzs, out, feats, Ws0, Ws1, Wt);        // 1
    ball_query_A_kernel<<<dim3(Mn / 8, 97), 256>>>(xyzs, Ws0);            // 2
    mlp_kernel<<<dim3(Mn * Kn / (64 * MLP_REPS), Bn * Sn * Jn), 256>>>(); // 3
    wt_kernel<<<dim3(Mn / 32, Bn * Sn), 256>>>(out + XYZ_TOTAL);          // 4
}

// round 14
// speedup vs baseline: 1.0407x; 1.0215x over previous
#include <cuda_runtime.h>
#include <cuda_bf16.h>

// Problem constants
#define Bn 4
#define Ln 8
#define Nn 4096
#define Mn 2048
#define Kn 32
#define Sn 8
#define Jn 3

// Staging buffers (device globals; no runtime allocation)
__device__ float g_anchors[Bn * Sn * Mn * 3];
__device__ float g_P[Bn * 8 * Nn * 64];
__device__ float g_A[Bn * Sn * Mn * 64];
__device__ int   g_idx[Bn * Sn * Jn * Mn * Kn];
__device__ float g_hmax[Bn * Sn * Jn * Mn * 128];        // [combo][m][r]
__device__ __nv_bfloat16 g_Ws1hi[128 * 64];              // Ws1 hi, [r][k] row-major
__device__ unsigned g_WsFragLo[8 * 4 * 32 * 4];          // Ws1 lo in mma A-frag layout
__device__ unsigned g_WtFragHi[3 * 16 * 8 * 32 * 4];     // Wt hi in mma A-frag layout
__device__ unsigned g_WtFragLo[3 * 16 * 8 * 32 * 4];     // Wt lo

// ---------------------------------------------------------------------------
// packed f32x2 helpers (per-lane IEEE rn — identical to __fadd_rn/__fmul_rn)
// ---------------------------------------------------------------------------
__device__ __forceinline__ unsigned long long f2pack(float lo, float hi) {
    unsigned long long r;
    asm("mov.b64 %0, {%1, %2};" : "=l"(r) : "f"(lo), "f"(hi));
    return r;
}
__device__ __forceinline__ void f2unpack(float& lo, float& hi, unsigned long long v) {
    asm("mov.b64 {%0, %1}, %2;" : "=f"(lo), "=f"(hi) : "l"(v));
}
__device__ __forceinline__ unsigned long long f2add(unsigned long long a,
                                                    unsigned long long b) {
    unsigned long long r;
    asm("add.rn.f32x2 %0, %1, %2;" : "=l"(r) : "l"(a), "l"(b));
    return r;
}
__device__ __forceinline__ unsigned long long f2mul(unsigned long long a,
                                                    unsigned long long b) {
    unsigned long long r;
    asm("mul.rn.f32x2 %0, %1, %2;" : "=l"(r) : "l"(a), "l"(b));
    return r;
}

// ---------------------------------------------------------------------------
// K1: FPS — standalone (R11 exact). Latency-critical; owns its 32 SMs.
// ---------------------------------------------------------------------------
__global__ void __launch_bounds__(256) fps_kernel(const float* __restrict__ xyzs,
                                                  float* __restrict__ out_xyz) {
    int bs = blockIdx.x;
    const float* xyz = xyzs + (size_t)bs * Nn * 3;
    __shared__ unsigned long long skey[2][8];

    int t = threadIdx.x;
    int lane = t & 31, wid = t >> 5;

    unsigned long long pxx[8], pyy[8], pzz[8];
    float pd[16];
#pragma unroll
    for (int i = 0; i < 8; i++) {
        int p0 = t + (2 * i) * 256;
        int p1 = t + (2 * i + 1) * 256;
        pxx[i] = f2pack(xyz[3 * p0], xyz[3 * p1]);
        pyy[i] = f2pack(xyz[3 * p0 + 1], xyz[3 * p1 + 1]);
        pzz[i] = f2pack(xyz[3 * p0 + 2], xyz[3 * p1 + 2]);
        pd[2 * i] = 1e10f;
        pd[2 * i + 1] = 1e10f;
    }
    float cx = xyz[0], cy = xyz[1], cz = xyz[2];

    float* oanc = g_anchors + (size_t)bs * Mn * 3;
    float* oxyz = out_xyz + (size_t)bs * Mn * 3;

    for (int m = 0; m < Mn; m++) {
        if (t == 0) {
            oanc[3 * m] = cx; oanc[3 * m + 1] = cy; oanc[3 * m + 2] = cz;
            oxyz[3 * m] = cx; oxyz[3 * m + 1] = cy; oxyz[3 * m + 2] = cz;
        }
        unsigned long long vcx = f2pack(-cx, -cx);
        unsigned long long vcy = f2pack(-cy, -cy);
        unsigned long long vcz = f2pack(-cz, -cz);
        unsigned long long key = 0;
#pragma unroll
        for (int i = 0; i < 8; i++) {
            unsigned long long dx = f2add(pxx[i], vcx);
            unsigned long long dy = f2add(pyy[i], vcy);
            unsigned long long dz = f2add(pzz[i], vcz);
            unsigned long long ssum =
                f2add(f2add(f2mul(dx, dx), f2mul(dy, dy)), f2mul(dz, dz));
            float d0, d1;
            f2unpack(d0, d1, ssum);
            float nd0 = fminf(pd[2 * i], d0);
            float nd1 = fminf(pd[2 * i + 1], d1);
            pd[2 * i] = nd0;
            pd[2 * i + 1] = nd1;
            unsigned long long k0 =
                ((unsigned long long)__float_as_uint(nd0) << 32) |
                (unsigned)(0xFFFFFFFFu - (unsigned)(t + (2 * i) * 256));
            unsigned long long k1 =
                ((unsigned long long)__float_as_uint(nd1) << 32) |
                (unsigned)(0xFFFFFFFFu - (unsigned)(t + (2 * i + 1) * 256));
            key = (k0 > key) ? k0 : key;
            key = (k1 > key) ? k1 : key;
        }
#pragma unroll
        for (int off = 16; off > 0; off >>= 1) {
            unsigned long long k2 = __shfl_xor_sync(0xffffffffu, key, off);
            key = (k2 > key) ? k2 : key;
        }
        if (lane == 0) skey[m & 1][wid] = key;
        __syncthreads();
        unsigned long long kb = skey[m & 1][0];
#pragma unroll
        for (int wq = 1; wq < 8; wq++) {
            unsigned long long k2 = skey[m & 1][wq];
            kb = (k2 > kb) ? k2 : kb;
        }
        int widx = (int)(0xFFFFFFFFu - (unsigned)kb);
        cx = xyz[3 * widx]; cy = xyz[3 * widx + 1]; cz = xyz[3 * widx + 2];
    }
}

// ---------------------------------------------------------------------------
// K2 (merged, throughput-tolerant): blockIdx.y < 96: ball query (R11 scalar).
// y == 96: A projection. y == 97: P projection + wtfrag hi/lo + Ws1 prep
// (grid-stride). bq is occupancy-tolerant so sharing SMs is safe here.
// ---------------------------------------------------------------------------
__global__ void __launch_bounds__(256) ball_query_merged_kernel(
    const float* __restrict__ xyzs, const float* __restrict__ feats,
    const float* __restrict__ Ws0, const float* __restrict__ Ws1,
    const float* __restrict__ Wt) {
    int t = threadIdx.x;

    if (blockIdx.y == 96) {
        // ---------------- A projection ----------------
        __shared__ float w[64 * 3];
        for (int i = t; i < 64 * 3; i += 256) {
            int o = i / 3, c = i % 3;
            w[i] = Ws0[o * 6 + c];
        }
        __syncthreads();
        int ga = blockIdx.x * 256 + t;  // 0..65535
        const float* a = g_anchors + (size_t)ga * 3;
        float x = a[0], y = a[1], z = a[2];
        float4* o = (float4*)(g_A + (size_t)ga * 64);
#pragma unroll
        for (int oo = 0; oo < 64; oo += 4) {
            float4 r;
            const float* w0 = w + oo * 3;
            r.x = w0[0] * x + w0[1] * y + w0[2] * z;
            r.y = w0[3] * x + w0[4] * y + w0[5] * z;
            r.z = w0[6] * x + w0[7] * y + w0[8] * z;
            r.w = w0[9] * x + w0[10] * y + w0[11] * z;
            o[oo >> 2] = r;
        }
        return;
    }

    if (blockIdx.y == 97) {
        // ---------------- P projection + weight prep (grid-stride) --------
        __shared__ float w[64 * 6];
        for (int i = t; i < 64 * 6; i += 256) w[i] = Ws0[i];
        __syncthreads();
        int base = blockIdx.x * 256 + t;  // 0..65535

        for (int gp = base; gp < Bn * 8 * Nn; gp += 65536) {
            int n = gp & (Nn - 1);
            int bf = gp >> 12;
            const float* p = xyzs + (size_t)gp * 3;
            float x = p[0], y = p[1], z = p[2];
            const float* f = feats + (size_t)bf * 3 * Nn + n;
            float f0 = f[0], f1 = f[Nn], f2 = f[2 * Nn];
            float4* o = (float4*)(g_P + (size_t)gp * 64);
#pragma unroll
            for (int oo = 0; oo < 64; oo += 4) {
                float4 r;
                const float* w0 = w + oo * 6;
                r.x = w0[0] * x + w0[1] * y + w0[2] * z + w0[3] * f0 + w0[4] * f1 + w0[5] * f2;
                r.y = w0[6] * x + w0[7] * y + w0[8] * z + w0[9] * f0 + w0[10] * f1 + w0[11] * f2;
                r.z = w0[12] * x + w0[13] * y + w0[14] * z + w0[15] * f0 + w0[16] * f1 + w0[17] * f2;
                r.w = w0[18] * x + w0[19] * y + w0[20] * z + w0[21] * f0 + w0[22] * f1 + w0[23] * f2;
                o[oo >> 2] = r;
            }
        }

        // wtfrag hi + lo (49152 items each)
        for (int i = base; i < 3 * 16 * 8 * 32 * 4; i += 65536) {
            int q = i & 3, lane = (i >> 2) & 31, ks = (i >> 7) & 7, rb = (i >> 10) & 15, j = i >> 14;
            int row = rb * 16 + (lane >> 2) + (q & 1) * 8;
            int k = ks * 16 + (lane & 3) * 2 + ((q >> 1) & 1) * 8;
            float e0 = Wt[(j * 256 + row) * 128 + k];
            float e1 = Wt[(j * 256 + row) * 128 + k + 1];
            __nv_bfloat16 h0 = __float2bfloat16_rn(e0);
            __nv_bfloat16 h1 = __float2bfloat16_rn(e1);
            __nv_bfloat16 l0 = __float2bfloat16_rn(e0 - __bfloat162float(h0));
            __nv_bfloat16 l1 = __float2bfloat16_rn(e1 - __bfloat162float(h1));
            unsigned uh0 = *(unsigned short*)&h0, uh1 = *(unsigned short*)&h1;
            unsigned ul0 = *(unsigned short*)&l0, ul1 = *(unsigned short*)&l1;
            g_WtFragHi[i] = (uh1 << 16) | uh0;
            g_WtFragLo[i] = (ul1 << 16) | ul0;
        }

        // Ws1 prep (8192 items)
        if (base < 128 * 64) {
            g_Ws1hi[base] = __float2bfloat16_rn(Ws1[base]);
        }
        if (base < 8 * 4 * 32 * 4) {
            int q = base & 3, lane = (base >> 2) & 31, ks = (base >> 7) & 3, w8 = base >> 9;
            int row = w8 * 16 + (lane >> 2) + (q & 1) * 8;
            int k = ks * 16 + (lane & 3) * 2 + ((q >> 1) & 1) * 8;
            float e0 = Ws1[row * 64 + k];
            float e1 = Ws1[row * 64 + k + 1];
            __nv_bfloat16 h0 = __float2bfloat16_rn(e0);
            __nv_bfloat16 h1 = __float2bfloat16_rn(e1);
            __nv_bfloat16 l0 = __float2bfloat16_rn(e0 - __bfloat162float(h0));
            __nv_bfloat16 l1 = __float2bfloat16_rn(e1 - __bfloat162float(h1));
            unsigned ul0 = *(unsigned short*)&l0, ul1 = *(unsigned short*)&l1;
            g_WsFragLo[base] = (ul1 << 16) | ul0;
        }
        return;
    }

    // ---------------- ball query (R11 scalar math, exact) ----------------
    int combo = blockIdx.y;
    int j = combo % 3;
    int bs = combo / 3;
    int b = bs >> 3, s = bs & 7;
    int g = s - 1 + j;
    g = g < 0 ? 0 : (g > 7 ? 7 : g);
    int wid = t >> 5, lane = t & 31;
    int m = blockIdx.x * 8 + wid;

    const float* pts = xyzs + (size_t)(b * 8 + g) * Nn * 3;
    const float* anc = g_anchors + ((size_t)bs * Mn + m) * 3;
    float ax = anc[0], ay = anc[1], az = anc[2];
    int* out = g_idx + ((size_t)combo * Mn + m) * Kn;

    int found = 0, first = -1;
    unsigned lt = (1u << lane) - 1u;
    for (int base = 0; base < Nn && found < Kn; base += 128) {
        int n0 = base + 4 * lane;
        const float4* pp = (const float4*)(pts + 3 * n0);
        float4 v0 = pp[0];
        float4 v1 = pp[1];
        float4 v2 = pp[2];

        float dx, dy, dz;
        dx = __fsub_rn(v0.x, ax); dy = __fsub_rn(v0.y, ay); dz = __fsub_rn(v0.z, az);
        float d0 = __fadd_rn(__fadd_rn(__fmul_rn(dx, dx), __fmul_rn(dy, dy)), __fmul_rn(dz, dz));
        dx = __fsub_rn(v0.w, ax); dy = __fsub_rn(v1.x, ay); dz = __fsub_rn(v1.y, az);
        float d1 = __fadd_rn(__fadd_rn(__fmul_rn(dx, dx), __fmul_rn(dy, dy)), __fmul_rn(dz, dz));
        dx = __fsub_rn(v1.z, ax); dy = __fsub_rn(v1.w, ay); dz = __fsub_rn(v2.x, az);
        float d2 = __fadd_rn(__fadd_rn(__fmul_rn(dx, dx), __fmul_rn(dy, dy)), __fmul_rn(dz, dz));
        dx = __fsub_rn(v2.y, ax); dy = __fsub_rn(v2.z, ay); dz = __fsub_rn(v2.w, az);
        float d3 = __fadd_rn(__fadd_rn(__fmul_rn(dx, dx), __fmul_rn(dy, dy)), __fmul_rn(dz, dz));

        bool p0 = d0 < 0.25f, p1 = d1 < 0.25f, p2 = d2 < 0.25f, p3 = d3 < 0.25f;
        unsigned m0 = __ballot_sync(0xffffffffu, p0);
        unsigned m1 = __ballot_sync(0xffffffffu, p1);
        unsigned m2 = __ballot_sync(0xffffffffu, p2);
        unsigned m3 = __ballot_sync(0xffffffffu, p3);

        if (first < 0 && (m0 | m1 | m2 | m3)) {
            int c0 = m0 ? 4 * (__ffs(m0) - 1) + 0 : 0x7fffffff;
            int c1 = m1 ? 4 * (__ffs(m1) - 1) + 1 : 0x7fffffff;
            int c2 = m2 ? 4 * (__ffs(m2) - 1) + 2 : 0x7fffffff;
            int c3 = m3 ? 4 * (__ffs(m3) - 1) + 3 : 0x7fffffff;
            int cmin = c0 < c1 ? c0 : c1;
            cmin = c2 < cmin ? c2 : cmin;
            cmin = c3 < cmin ? c3 : cmin;
            first = base + cmin;
        }
        int pos = found + __popc(m0 & lt) + __popc(m1 & lt) +
                  __popc(m2 & lt) + __popc(m3 & lt);
        if (p0 && pos < Kn) out[pos] = n0;
        pos += p0 ? 1 : 0;
        if (p1 && pos < Kn) out[pos] = n0 + 1;
        pos += p1 ? 1 : 0;
        if (p2 && pos < Kn) out[pos] = n0 + 2;
        pos += p2 ? 1 : 0;
        if (p3 && pos < Kn) out[pos] = n0 + 3;
        found += __popc(m0) + __popc(m1) + __popc(m2) + __popc(m3);
    }
    if (found < Kn) {
        int pad = first < 0 ? 0 : first;
        for (int p = found + lane; p < Kn; p += 32) out[p] = pad;
    }
}

// ---------------------------------------------------------------------------
// mma / ldsm helpers
// ---------------------------------------------------------------------------
__device__ __forceinline__ void mma_bf16(float c[4], const unsigned a[4],
                                         unsigned b0, unsigned b1) {
    asm volatile(
        "mma.sync.aligned.m16n8k16.row.col.f32.bf16.bf16.f32 "
        "{%0,%1,%2,%3}, {%4,%5,%6,%7}, {%8,%9}, {%0,%1,%2,%3};"
        : "+f"(c[0]), "+f"(c[1]), "+f"(c[2]), "+f"(c[3])
        : "r"(a[0]), "r"(a[1]), "r"(a[2]), "r"(a[3]), "r"(b0), "r"(b1));
}

__device__ __forceinline__ void ldsm4(unsigned r[4], unsigned saddr) {
    asm volatile(
        "ldmatrix.sync.aligned.m8n8.x4.shared.b16 {%0,%1,%2,%3}, [%4];"
        : "=r"(r[0]), "=r"(r[1]), "=r"(r[2]), "=r"(r[3])
        : "r"(saddr));
}

// ---------------------------------------------------------------------------
// K3: mlp (R11 exact — 32x32 warp tile, REPS=8)
// ---------------------------------------------------------------------------
#define MLP_REPS 8

__global__ void __launch_bounds__(256, 2) mlp_kernel() {
    __shared__ __align__(16) __nv_bfloat16 Whi[128 * 64];
    __shared__ __align__(16) __nv_bfloat16 Bhs[2][64 * 64];
    __shared__ __align__(16) __nv_bfloat16 Bls[2][64 * 64];

    int t = threadIdx.x;
    int lane = t & 31, w = t >> 5;
    int mt = w >> 1;
    int nh = w & 1;
    int combo = blockIdx.y;
    int j = combo % 3;
    int bs = combo / 3;
    int b = bs >> 3, s = bs & 7;
    int g = s - 1 + j;
    g = g < 0 ? 0 : (g > 7 ? 7 : g);

    {
        const uint4* gh = (const uint4*)g_Ws1hi;
        uint4* sh = (uint4*)Whi;
        for (int i = t; i < 1024; i += 256) {
            int r = i >> 3, c = i & 7;
            sh[(r << 3) + (c ^ (r & 7))] = gh[i];
        }
    }
    __syncthreads();

    unsigned sWhi = (unsigned)__cvta_generic_to_shared(Whi);
    unsigned sBh0 = (unsigned)__cvta_generic_to_shared(Bhs[0]);
    unsigned sBl0 = (unsigned)__cvta_generic_to_shared(Bls[0]);

    unsigned ahi[2][4][4];
#pragma unroll
    for (int mi = 0; mi < 2; mi++) {
        int r = mt * 32 + mi * 16 + (lane & 15);
#pragma unroll
        for (int ks = 0; ks < 4; ks++) {
            int chunk = ks * 2 + (lane >> 4);
            ldsm4(ahi[mi][ks], sWhi + r * 128 + ((chunk ^ (r & 7)) << 4));
        }
    }

    int col = t & 63;
    int kq = t >> 6;
    int brow_base = (lane & 7) + ((lane & 16) >> 1);
    int bksel = (lane >> 3) & 1;

    const float4* Pbase = (const float4*)(g_P + (size_t)(b * 8 + g) * Nn * 64);
    const float4* Abase = (const float4*)(g_A + (size_t)bs * Mn * 64);
    const int* idxbase = g_idx + (size_t)combo * Mn * Kn;
    const uint4* fragLoV = (const uint4*)g_WsFragLo;

    float4 pf_p[4];
    int mcur;

    {
        int gcol = blockIdx.x * MLP_REPS * 64 + col;
        mcur = gcol >> 5;
        int knb = gcol & 31;
        int n = idxbase[mcur * Kn + knb];
        const float4* Prow = Pbase + (size_t)n * 16;
#pragma unroll
        for (int q = 0; q < 4; q++) pf_p[q] = Prow[kq * 4 + q];
    }
    {
        const float4* Arow = Abase + (size_t)mcur * 16;
        char* bh = (char*)Bhs[0];
        char* bl = (char*)Bls[0];
#pragma unroll
        for (int q = 0; q < 4; q++) {
            float4 a4 = Arow[kq * 4 + q];
            float h0 = fmaxf(pf_p[q].x - a4.x, 0.f);
            float h1 = fmaxf(pf_p[q].y - a4.y, 0.f);
            float h2 = fmaxf(pf_p[q].z - a4.z, 0.f);
            float h3 = fmaxf(pf_p[q].w - a4.w, 0.f);
            __nv_bfloat162 hiA, hiB, loA, loB;
            hiA.x = __float2bfloat16_rn(h0); hiA.y = __float2bfloat16_rn(h1);
            hiB.x = __float2bfloat16_rn(h2); hiB.y = __float2bfloat16_rn(h3);
            loA.x = __float2bfloat16_rn(h0 - __bfloat162float(hiA.x));
            loA.y = __float2bfloat16_rn(h1 - __bfloat162float(hiA.y));
            loB.x = __float2bfloat16_rn(h2 - __bfloat162float(hiB.x));
            loB.y = __float2bfloat16_rn(h3 - __bfloat162float(hiB.y));
            int k0 = kq * 16 + q * 4;
            int chunk = k0 >> 3;
            int off = col * 128 + ((chunk ^ (col & 7)) << 4) + ((k0 & 7) << 1);
            uint2 vh, vl;
            vh.x = *(unsigned*)&hiA; vh.y = *(unsigned*)&hiB;
            vl.x = *(unsigned*)&loA; vl.y = *(unsigned*)&loB;
            *(uint2*)(bh + off) = vh;
            *(uint2*)(bl + off) = vl;
        }
    }
    __syncthreads();

    for (int rep = 0; rep < MLP_REPS; rep++) {
        int buf = rep & 1;
        int mnext = mcur;
        if (rep + 1 < MLP_REPS) {
            int gcol = (blockIdx.x * MLP_REPS + rep + 1) * 64 + col;
            mnext = gcol >> 5;
            int knb = gcol & 31;
            int n = idxbase[mnext * Kn + knb];
            const float4* Prow = Pbase + (size_t)n * 16;
#pragma unroll
            for (int q = 0; q < 4; q++) pf_p[q] = Prow[kq * 4 + q];
        }

        float acc[2][4][4];
#pragma unroll
        for (int mi = 0; mi < 2; mi++)
#pragma unroll
            for (int nt = 0; nt < 4; nt++)
#pragma unroll
                for (int i = 0; i < 4; i++) acc[mi][nt][i] = 0.f;

        unsigned sBh = sBh0 + buf * 8192;
        unsigned sBl = sBl0 + buf * 8192;
#pragma unroll
        for (int ks = 0; ks < 4; ks++) {
            uint4 fl0 = fragLoV[((mt * 2 + 0) * 4 + ks) * 32 + lane];
            uint4 fl1 = fragLoV[((mt * 2 + 1) * 4 + ks) * 32 + lane];
            unsigned alo0[4] = {fl0.x, fl0.y, fl0.z, fl0.w};
            unsigned alo1[4] = {fl1.x, fl1.y, fl1.z, fl1.w};
            int chunk = ks * 2 + bksel;
#pragma unroll
            for (int p = 0; p < 2; p++) {
                int r = nh * 32 + p * 16 + brow_base;
                unsigned off = r * 128 + ((chunk ^ (r & 7)) << 4);
                unsigned hh[4], ll[4];
                ldsm4(hh, sBh + off);
                ldsm4(ll, sBl + off);
                mma_bf16(acc[0][2 * p],     ahi[0][ks], hh[0], hh[1]);
                mma_bf16(acc[0][2 * p + 1], ahi[0][ks], hh[2], hh[3]);
                mma_bf16(acc[1][2 * p],     ahi[1][ks], hh[0], hh[1]);
                mma_bf16(acc[1][2 * p + 1], ahi[1][ks], hh[2], hh[3]);
                mma_bf16(acc[0][2 * p],     ahi[0][ks], ll[0], ll[1]);
                mma_bf16(acc[0][2 * p + 1], ahi[0][ks], ll[2], ll[3]);
                mma_bf16(acc[1][2 * p],     ahi[1][ks], ll[0], ll[1]);
                mma_bf16(acc[1][2 * p + 1], ahi[1][ks], ll[2], ll[3]);
                mma_bf16(acc[0][2 * p],     alo0,       hh[0], hh[1]);
                mma_bf16(acc[0][2 * p + 1], alo0,       hh[2], hh[3]);
                mma_bf16(acc[1][2 * p],     alo1,       hh[0], hh[1]);
                mma_bf16(acc[1][2 * p + 1], alo1,       hh[2], hh[3]);
            }
        }

        if (rep + 1 < MLP_REPS) {
            const float4* Arow = Abase + (size_t)mnext * 16;
            char* bh = (char*)Bhs[buf ^ 1];
            char* bl = (char*)Bls[buf ^ 1];
#pragma unroll
            for (int q = 0; q < 4; q++) {
                float4 a4 = Arow[kq * 4 + q];
                float h0 = fmaxf(pf_p[q].x - a4.x, 0.f);
                float h1 = fmaxf(pf_p[q].y - a4.y, 0.f);
                float h2 = fmaxf(pf_p[q].z - a4.z, 0.f);
                float h3 = fmaxf(pf_p[q].w - a4.w, 0.f);
                __nv_bfloat162 hiA, hiB, loA, loB;
                hiA.x = __float2bfloat16_rn(h0); hiA.y = __float2bfloat16_rn(h1);
                hiB.x = __float2bfloat16_rn(h2); hiB.y = __float2bfloat16_rn(h3);
                loA.x = __float2bfloat16_rn(h0 - __bfloat162float(hiA.x));
                loA.y = __float2bfloat16_rn(h1 - __bfloat162float(hiA.y));
                loB.x = __float2bfloat16_rn(h2 - __bfloat162float(hiB.x));
                loB.y = __float2bfloat16_rn(h3 - __bfloat162float(hiB.y));
                int k0 = kq * 16 + q * 4;
                int chunk = k0 >> 3;
                int off = col * 128 + ((chunk ^ (col & 7)) << 4) + ((k0 & 7) << 1);
                uint2 vh, vl;
                vh.x = *(unsigned*)&hiA; vh.y = *(unsigned*)&hiB;
                vl.x = *(unsigned*)&loA; vl.y = *(unsigned*)&loB;
                *(uint2*)(bh + off) = vh;
                *(uint2*)(bl + off) = vl;
            }
        }
        mcur = mnext;

        int mbase = (blockIdx.x * MLP_REPS + rep) * 2;
        int grp = lane >> 2;
#pragma unroll
        for (int mi = 0; mi < 2; mi++) {
            float m0 = -1e30f, m1 = -1e30f;
#pragma unroll
            for (int nt = 0; nt < 4; nt++) {
                m0 = fmaxf(m0, fmaxf(acc[mi][nt][0], acc[mi][nt][1]));
                m1 = fmaxf(m1, fmaxf(acc[mi][nt][2], acc[mi][nt][3]));
            }
            m0 = fmaxf(m0, __shfl_xor_sync(0xffffffffu, m0, 1));
            m0 = fmaxf(m0, __shfl_xor_sync(0xffffffffu, m0, 2));
            m1 = fmaxf(m1, __shfl_xor_sync(0xffffffffu, m1, 1));
            m1 = fmaxf(m1, __shfl_xor_sync(0xffffffffu, m1, 2));
            if ((lane & 3) == 0) {
                float* o = g_hmax + ((size_t)combo * Mn + mbase + nh) * 128 +
                           mt * 32 + mi * 16 + grp;
                o[0] = fmaxf(m0, 0.f);
                o[8] = fmaxf(m1, 0.f);
            }
        }
        __syncthreads();
    }
}

// ---------------------------------------------------------------------------
// K4: wt on tensor cores (unchanged)
// ---------------------------------------------------------------------------
__device__ __forceinline__ void wt_produce(char* bh, char* bl, const float4* pf,
                                           int col, int kq) {
#pragma unroll
    for (int q = 0; q < 4; q++) {
        float4 v = pf[q];
        __nv_bfloat162 hiA, hiB, loA, loB;
        hiA.x = __float2bfloat16_rn(v.x); hiA.y = __float2bfloat16_rn(v.y);
        hiB.x = __float2bfloat16_rn(v.z); hiB.y = __float2bfloat16_rn(v.w);
        loA.x = __float2bfloat16_rn(v.x - __bfloat162float(hiA.x));
        loA.y = __float2bfloat16_rn(v.y - __bfloat162float(hiA.y));
        loB.x = __float2bfloat16_rn(v.z - __bfloat162float(hiB.x));
        loB.y = __float2bfloat16_rn(v.w - __bfloat162float(hiB.y));
        int k0 = kq * 16 + q * 4;
        int chunk = k0 >> 3;
        int off = col * 256 + ((chunk ^ (col & 7)) << 4) + ((k0 & 7) << 1);
        uint2 vh, vl;
        vh.x = *(unsigned*)&hiA; vh.y = *(unsigned*)&hiB;
        vl.x = *(unsigned*)&loA; vl.y = *(unsigned*)&loB;
        *(uint2*)(bh + off) = vh;
        *(uint2*)(bl + off) = vl;
    }
}

__global__ void __launch_bounds__(256) wt_kernel(float* __restrict__ outf) {
    __shared__ __align__(16) __nv_bfloat16 Bh[2][32 * 128];
    __shared__ __align__(16) __nv_bfloat16 Bl[2][32 * 128];

    int t = threadIdx.x;
    int lane = t & 31, w = t >> 5;
    int bs = blockIdx.y;
    int mbase = blockIdx.x * 32;

    int col = t >> 3;
    int kq = t & 7;
    int brow_base = (lane & 7) + ((lane & 16) >> 1);
    int bksel = (lane >> 3) & 1;

    unsigned sBh0 = (unsigned)__cvta_generic_to_shared(Bh[0]);
    unsigned sBl0 = (unsigned)__cvta_generic_to_shared(Bl[0]);

    float4 pf[4];
    {
        const float4* src = (const float4*)(g_hmax +
            (((size_t)(bs * 3 + 0)) * Mn + mbase + col) * 128 + kq * 16);
#pragma unroll
        for (int q = 0; q < 4; q++) pf[q] = src[q];
    }
    wt_produce((char*)Bh[0], (char*)Bl[0], pf, col, kq);
    __syncthreads();

    float tot[2][4][4];
#pragma unroll
    for (int mt = 0; mt < 2; mt++)
#pragma unroll
        for (int nt = 0; nt < 4; nt++)
#pragma unroll
            for (int i = 0; i < 4; i++) tot[mt][nt][i] = 0.f;

    const uint4* fragHi = (const uint4*)g_WtFragHi;
    const uint4* fragLo = (const uint4*)g_WtFragLo;

#pragma unroll
    for (int j = 0; j < 3; j++) {
        if (j < 2) {
            const float4* src = (const float4*)(g_hmax +
                (((size_t)(bs * 3 + j + 1)) * Mn + mbase + col) * 128 + kq * 16);
#pragma unroll
            for (int q = 0; q < 4; q++) pf[q] = src[q];
        }

        float acc[2][4][4];
#pragma unroll
        for (int mt = 0; mt < 2; mt++)
#pragma unroll
            for (int nt = 0; nt < 4; nt++)
#pragma unroll
                for (int i = 0; i < 4; i++) acc[mt][nt][i] = 0.f;

        unsigned sBhj = sBh0 + (j & 1) * 8192;
        unsigned sBlj = sBl0 + (j & 1) * 8192;

#pragma unroll
        for (int ks = 0; ks < 8; ks++) {
            uint4 fh0 = fragHi[((j * 16 + w * 2 + 0) * 8 + ks) * 32 + lane];
            uint4 fl0 = fragLo[((j * 16 + w * 2 + 0) * 8 + ks) * 32 + lane];
            uint4 fh1 = fragHi[((j * 16 + w * 2 + 1) * 8 + ks) * 32 + lane];
            uint4 fl1 = fragLo[((j * 16 + w * 2 + 1) * 8 + ks) * 32 + lane];
            unsigned ah0[4] = {fh0.x, fh0.y, fh0.z, fh0.w};
            unsigned al0[4] = {fl0.x, fl0.y, fl0.z, fl0.w};
            unsigned ah1[4] = {fh1.x, fh1.y, fh1.z, fh1.w};
            unsigned al1[4] = {fl1.x, fl1.y, fl1.z, fl1.w};
            int chunk = ks * 2 + bksel;
#pragma unroll
            for (int p = 0; p < 2; p++) {
                int r = p * 16 + brow_base;
                unsigned off = r * 256 + ((chunk ^ (r & 7)) << 4);
                unsigned hh[4], ll[4];
                ldsm4(hh, sBhj + off);
                ldsm4(ll, sBlj + off);
                mma_bf16(acc[0][2 * p],     ah0, hh[0], hh[1]);
                mma_bf16(acc[0][2 * p],     ah0, ll[0], ll[1]);
                mma_bf16(acc[0][2 * p],     al0, hh[0], hh[1]);
                mma_bf16(acc[0][2 * p + 1], ah0, hh[2], hh[3]);
                mma_bf16(acc[0][2 * p + 1], ah0, ll[2], ll[3]);
                mma_bf16(acc[0][2 * p + 1], al0, hh[2], hh[3]);
                mma_bf16(acc[1][2 * p],     ah1, hh[0], hh[1]);
                mma_bf16(acc[1][2 * p],     ah1, ll[0], ll[1]);
                mma_bf16(acc[1][2 * p],     al1, hh[0], hh[1]);
                mma_bf16(acc[1][2 * p + 1], ah1, hh[2], hh[3]);
                mma_bf16(acc[1][2 * p + 1], ah1, ll[2], ll[3]);
                mma_bf16(acc[1][2 * p + 1], al1, hh[2], hh[3]);
            }
        }

        if (j < 2)
            wt_produce((char*)Bh[(j + 1) & 1], (char*)Bl[(j + 1) & 1], pf, col, kq);

#pragma unroll
        for (int mt = 0; mt < 2; mt++)
#pragma unroll
            for (int nt = 0; nt < 4; nt++)
#pragma unroll
                for (int i = 0; i < 4; i++)
                    tot[mt][nt][i] += fmaxf(acc[mt][nt][i], 0.f);
        __syncthreads();
    }

#pragma unroll
    for (int mt = 0; mt < 2; mt++) {
        int row = w * 32 + mt * 16 + (lane >> 2);
#pragma unroll
        for (int nt = 0; nt < 4; nt++) {
            int c = mbase + nt * 8 + (lane & 3) * 2;
            float2 v0; v0.x = tot[mt][nt][0]; v0.y = tot[mt][nt][1];
            float2 v1; v1.x = tot[mt][nt][2]; v1.y = tot[mt][nt][3];
            *(float2*)&outf[((size_t)bs * 256 + row) * Mn + c] = v0;
            *(float2*)&outf[((size_t)bs * 256 + row + 8) * Mn + c] = v1;
        }
    }
}

// ---------------------------------------------------------------------------
extern "C" void kernel_launch(void* const* d_in, const int* in_sizes, int n_in,
                              void* d_out, int out_size) {
    const float* xyzs = (const float*)d_in[0];
    const float* feats = (const float*)d_in[1];
    const float* Ws0 = (const float*)d_in[2];
    const float* Ws1 = (const float*)d_in[3];
    const float* Wt = (const float*)d_in[4];
    float* out = (float*)d_out;

    const int XYZ_TOTAL = Bn * Sn * Mn * 3;  // 196608

    fps_kernel<<<Bn * Sn, 256>>>(xyzs, out);                               // 1 (isolated)
    ball_query_merged_kernel<<<dim3(Mn / 8, 98), 256>>>(xyzs, feats, Ws0,
                                                        Ws1, Wt);          // 2
    mlp_kernel<<<dim3(Mn * Kn / (64 * MLP_REPS), Bn * Sn * Jn), 256>>>();  // 3
    wt_kernel<<<dim3(Mn / 32, Bn * Sn), 256>>>(out + XYZ_TOTAL);           // 4
}

// round 15
// speedup vs baseline: 1.1036x; 1.0604x over previous
#include <cuda_runtime.h>
#include <cuda_bf16.h>

// Problem constants
#define Bn 4
#define Ln 8
#define Nn 4096
#define Mn 2048
#define Kn 32
#define Sn 8
#define Jn 3

// Staging buffers (device globals; no runtime allocation)
__device__ float g_anchors[Bn * Sn * Mn * 3];
__device__ float g_P[Bn * 8 * Nn * 64];
__device__ float g_A[Bn * Sn * Mn * 64];
__device__ int   g_idx[Bn * Sn * Jn * Mn * Kn];
__device__ float g_hmax[Bn * Sn * Jn * Mn * 128];        // [combo][m][r]
__device__ __nv_bfloat16 g_Ws1hi[128 * 64];              // Ws1 hi, [r][k] row-major
__device__ unsigned g_WsFragLo[8 * 4 * 32 * 4];          // Ws1 lo in mma A-frag layout
__device__ unsigned g_WtFragHi[3 * 16 * 8 * 32 * 4];     // Wt hi in mma A-frag layout
__device__ unsigned g_WtFragLo[3 * 16 * 8 * 32 * 4];     // Wt lo

// ---------------------------------------------------------------------------
// packed f32x2 helpers (per-lane IEEE rn)
// ---------------------------------------------------------------------------
__device__ __forceinline__ unsigned long long f2pack(float lo, float hi) {
    unsigned long long r;
    asm("mov.b64 %0, {%1, %2};" : "=l"(r) : "f"(lo), "f"(hi));
    return r;
}
__device__ __forceinline__ void f2unpack(float& lo, float& hi, unsigned long long v) {
    asm("mov.b64 {%0, %1}, %2;" : "=f"(lo), "=f"(hi) : "l"(v));
}
__device__ __forceinline__ unsigned long long f2add(unsigned long long a,
                                                    unsigned long long b) {
    unsigned long long r;
    asm("add.rn.f32x2 %0, %1, %2;" : "=l"(r) : "l"(a), "l"(b));
    return r;
}
__device__ __forceinline__ unsigned long long f2mul(unsigned long long a,
                                                    unsigned long long b) {
    unsigned long long r;
    asm("mul.rn.f32x2 %0, %1, %2;" : "=l"(r) : "l"(a), "l"(b));
    return r;
}

// ---------------------------------------------------------------------------
// K1: FPS (R11 exact — standalone, latency-critical)
// ---------------------------------------------------------------------------
__global__ void __launch_bounds__(256) fps_kernel(const float* __restrict__ xyzs,
                                                  float* __restrict__ out_xyz) {
    int bs = blockIdx.x;
    const float* xyz = xyzs + (size_t)bs * Nn * 3;
    __shared__ unsigned long long skey[2][8];

    int t = threadIdx.x;
    int lane = t & 31, wid = t >> 5;

    unsigned long long pxx[8], pyy[8], pzz[8];
    float pd[16];
#pragma unroll
    for (int i = 0; i < 8; i++) {
        int p0 = t + (2 * i) * 256;
        int p1 = t + (2 * i + 1) * 256;
        pxx[i] = f2pack(xyz[3 * p0], xyz[3 * p1]);
        pyy[i] = f2pack(xyz[3 * p0 + 1], xyz[3 * p1 + 1]);
        pzz[i] = f2pack(xyz[3 * p0 + 2], xyz[3 * p1 + 2]);
        pd[2 * i] = 1e10f;
        pd[2 * i + 1] = 1e10f;
    }
    float cx = xyz[0], cy = xyz[1], cz = xyz[2];

    float* oanc = g_anchors + (size_t)bs * Mn * 3;
    float* oxyz = out_xyz + (size_t)bs * Mn * 3;

    for (int m = 0; m < Mn; m++) {
        if (t == 0) {
            oanc[3 * m] = cx; oanc[3 * m + 1] = cy; oanc[3 * m + 2] = cz;
            oxyz[3 * m] = cx; oxyz[3 * m + 1] = cy; oxyz[3 * m + 2] = cz;
        }
        unsigned long long vcx = f2pack(-cx, -cx);
        unsigned long long vcy = f2pack(-cy, -cy);
        unsigned long long vcz = f2pack(-cz, -cz);
        unsigned long long key = 0;
#pragma unroll
        for (int i = 0; i < 8; i++) {
            unsigned long long dx = f2add(pxx[i], vcx);
            unsigned long long dy = f2add(pyy[i], vcy);
            unsigned long long dz = f2add(pzz[i], vcz);
            unsigned long long ssum =
                f2add(f2add(f2mul(dx, dx), f2mul(dy, dy)), f2mul(dz, dz));
            float d0, d1;
            f2unpack(d0, d1, ssum);
            float nd0 = fminf(pd[2 * i], d0);
            float nd1 = fminf(pd[2 * i + 1], d1);
            pd[2 * i] = nd0;
            pd[2 * i + 1] = nd1;
            unsigned long long k0 =
                ((unsigned long long)__float_as_uint(nd0) << 32) |
                (unsigned)(0xFFFFFFFFu - (unsigned)(t + (2 * i) * 256));
            unsigned long long k1 =
                ((unsigned long long)__float_as_uint(nd1) << 32) |
                (unsigned)(0xFFFFFFFFu - (unsigned)(t + (2 * i + 1) * 256));
            key = (k0 > key) ? k0 : key;
            key = (k1 > key) ? k1 : key;
        }
#pragma unroll
        for (int off = 16; off > 0; off >>= 1) {
            unsigned long long k2 = __shfl_xor_sync(0xffffffffu, key, off);
            key = (k2 > key) ? k2 : key;
        }
        if (lane == 0) skey[m & 1][wid] = key;
        __syncthreads();
        unsigned long long kb = skey[m & 1][0];
#pragma unroll
        for (int wq = 1; wq < 8; wq++) {
            unsigned long long k2 = skey[m & 1][wq];
            kb = (k2 > kb) ? k2 : kb;
        }
        int widx = (int)(0xFFFFFFFFu - (unsigned)kb);
        cx = xyz[3 * widx]; cy = xyz[3 * widx + 1]; cz = xyz[3 * widx + 2];
    }
}

// ---------------------------------------------------------------------------
// K2: P + A + Ws1 prep (R11 exact)
// ---------------------------------------------------------------------------
__global__ void __launch_bounds__(256) compute_PA(const float* __restrict__ xyzs,
                                                  const float* __restrict__ feats,
                                                  const float* __restrict__ Ws0,
                                                  const float* __restrict__ Ws1) {
    int t = threadIdx.x;
    if (blockIdx.x < 512) {
        __shared__ float w[64 * 6];
        for (int i = t; i < 64 * 6; i += 256) w[i] = Ws0[i];
        __syncthreads();

        int gp = blockIdx.x * 256 + t;
        int n = gp & (Nn - 1);
        int bf = gp >> 12;
        const float* p = xyzs + (size_t)gp * 3;
        float x = p[0], y = p[1], z = p[2];
        const float* f = feats + (size_t)bf * 3 * Nn + n;
        float f0 = f[0], f1 = f[Nn], f2 = f[2 * Nn];
        float4* o = (float4*)(g_P + (size_t)gp * 64);
#pragma unroll
        for (int oo = 0; oo < 64; oo += 4) {
            float4 r;
            const float* w0 = w + oo * 6;
            r.x = w0[0] * x + w0[1] * y + w0[2] * z + w0[3] * f0 + w0[4] * f1 + w0[5] * f2;
            r.y = w0[6] * x + w0[7] * y + w0[8] * z + w0[9] * f0 + w0[10] * f1 + w0[11] * f2;
            r.z = w0[12] * x + w0[13] * y + w0[14] * z + w0[15] * f0 + w0[16] * f1 + w0[17] * f2;
            r.w = w0[18] * x + w0[19] * y + w0[20] * z + w0[21] * f0 + w0[22] * f1 + w0[23] * f2;
            o[oo >> 2] = r;
        }
    } else {
        __shared__ float w[64 * 3];
        for (int i = t; i < 64 * 3; i += 256) {
            int o = i / 3, c = i % 3;
            w[i] = Ws0[o * 6 + c];
        }
        __syncthreads();
        int ga = (blockIdx.x - 512) * 256 + t;
        const float* a = g_anchors + (size_t)ga * 3;
        float x = a[0], y = a[1], z = a[2];
        float4* o = (float4*)(g_A + (size_t)ga * 64);
#pragma unroll
        for (int oo = 0; oo < 64; oo += 4) {
            float4 r;
            const float* w0 = w + oo * 3;
            r.x = w0[0] * x + w0[1] * y + w0[2] * z;
            r.y = w0[3] * x + w0[4] * y + w0[5] * z;
            r.z = w0[6] * x + w0[7] * y + w0[8] * z;
            r.w = w0[9] * x + w0[10] * y + w0[11] * z;
            o[oo >> 2] = r;
        }
        if (ga < 128 * 64) {
            g_Ws1hi[ga] = __float2bfloat16_rn(Ws1[ga]);
        }
        if (ga < 8 * 4 * 32 * 4) {
            int q = ga & 3, lane = (ga >> 2) & 31, ks = (ga >> 7) & 3, w8 = ga >> 9;
            int row = w8 * 16 + (lane >> 2) + (q & 1) * 8;
            int k = ks * 16 + (lane & 3) * 2 + ((q >> 1) & 1) * 8;
            float e0 = Ws1[row * 64 + k];
            float e1 = Ws1[row * 64 + k + 1];
            __nv_bfloat16 h0 = __float2bfloat16_rn(e0);
            __nv_bfloat16 h1 = __float2bfloat16_rn(e1);
            __nv_bfloat16 l0 = __float2bfloat16_rn(e0 - __bfloat162float(h0));
            __nv_bfloat16 l1 = __float2bfloat16_rn(e1 - __bfloat162float(h1));
            unsigned ul0 = *(unsigned short*)&l0, ul1 = *(unsigned short*)&l1;
            g_WsFragLo[ga] = (ul1 << 16) | ul0;
        }
    }
}

// ---------------------------------------------------------------------------
// K3: ball query — 4 points/lane, scalar math (R11 exact)
// ---------------------------------------------------------------------------
__global__ void __launch_bounds__(256) ball_query_kernel(const float* __restrict__ xyzs) {
    int combo = blockIdx.y;
    int j = combo % 3;
    int bs = combo / 3;
    int b = bs >> 3, s = bs & 7;
    int g = s - 1 + j;
    g = g < 0 ? 0 : (g > 7 ? 7 : g);
    int wid = threadIdx.x >> 5, lane = threadIdx.x & 31;
    int m = blockIdx.x * 8 + wid;

    const float* pts = xyzs + (size_t)(b * 8 + g) * Nn * 3;
    const float* anc = g_anchors + ((size_t)bs * Mn + m) * 3;
    float ax = anc[0], ay = anc[1], az = anc[2];
    int* out = g_idx + ((size_t)combo * Mn + m) * Kn;

    int found = 0, first = -1;
    unsigned lt = (1u << lane) - 1u;
    for (int base = 0; base < Nn && found < Kn; base += 128) {
        int n0 = base + 4 * lane;
        const float4* pp = (const float4*)(pts + 3 * n0);
        float4 v0 = pp[0];
        float4 v1 = pp[1];
        float4 v2 = pp[2];

        float dx, dy, dz;
        dx = __fsub_rn(v0.x, ax); dy = __fsub_rn(v0.y, ay); dz = __fsub_rn(v0.z, az);
        float d0 = __fadd_rn(__fadd_rn(__fmul_rn(dx, dx), __fmul_rn(dy, dy)), __fmul_rn(dz, dz));
        dx = __fsub_rn(v0.w, ax); dy = __fsub_rn(v1.x, ay); dz = __fsub_rn(v1.y, az);
        float d1 = __fadd_rn(__fadd_rn(__fmul_rn(dx, dx), __fmul_rn(dy, dy)), __fmul_rn(dz, dz));
        dx = __fsub_rn(v1.z, ax); dy = __fsub_rn(v1.w, ay); dz = __fsub_rn(v2.x, az);
        float d2 = __fadd_rn(__fadd_rn(__fmul_rn(dx, dx), __fmul_rn(dy, dy)), __fmul_rn(dz, dz));
        dx = __fsub_rn(v2.y, ax); dy = __fsub_rn(v2.z, ay); dz = __fsub_rn(v2.w, az);
        float d3 = __fadd_rn(__fadd_rn(__fmul_rn(dx, dx), __fmul_rn(dy, dy)), __fmul_rn(dz, dz));

        bool p0 = d0 < 0.25f, p1 = d1 < 0.25f, p2 = d2 < 0.25f, p3 = d3 < 0.25f;
        unsigned m0 = __ballot_sync(0xffffffffu, p0);
        unsigned m1 = __ballot_sync(0xffffffffu, p1);
        unsigned m2 = __ballot_sync(0xffffffffu, p2);
        unsigned m3 = __ballot_sync(0xffffffffu, p3);

        if (first < 0 && (m0 | m1 | m2 | m3)) {
            int c0 = m0 ? 4 * (__ffs(m0) - 1) + 0 : 0x7fffffff;
            int c1 = m1 ? 4 * (__ffs(m1) - 1) + 1 : 0x7fffffff;
            int c2 = m2 ? 4 * (__ffs(m2) - 1) + 2 : 0x7fffffff;
            int c3 = m3 ? 4 * (__ffs(m3) - 1) + 3 : 0x7fffffff;
            int cmin = c0 < c1 ? c0 : c1;
            cmin = c2 < cmin ? c2 : cmin;
            cmin = c3 < cmin ? c3 : cmin;
            first = base + cmin;
        }
        int pos = found + __popc(m0 & lt) + __popc(m1 & lt) +
                  __popc(m2 & lt) + __popc(m3 & lt);
        if (p0 && pos < Kn) out[pos] = n0;
        pos += p0 ? 1 : 0;
        if (p1 && pos < Kn) out[pos] = n0 + 1;
        pos += p1 ? 1 : 0;
        if (p2 && pos < Kn) out[pos] = n0 + 2;
        pos += p2 ? 1 : 0;
        if (p3 && pos < Kn) out[pos] = n0 + 3;
        found += __popc(m0) + __popc(m1) + __popc(m2) + __popc(m3);
    }
    if (found < Kn) {
        int pad = first < 0 ? 0 : first;
        for (int p = found + lane; p < Kn; p += 32) out[p] = pad;
    }
}

// ---------------------------------------------------------------------------
// Wt A-frag packing (R11 exact — standalone kernels)
// ---------------------------------------------------------------------------
__global__ void __launch_bounds__(256) wtfrag_hi(const float* __restrict__ Wt) {
    int i = blockIdx.x * 256 + threadIdx.x;
    int q = i & 3, lane = (i >> 2) & 31, ks = (i >> 7) & 7, rb = (i >> 10) & 15, j = i >> 14;
    int row = rb * 16 + (lane >> 2) + (q & 1) * 8;
    int k = ks * 16 + (lane & 3) * 2 + ((q >> 1) & 1) * 8;
    float e0 = Wt[(j * 256 + row) * 128 + k];
    float e1 = Wt[(j * 256 + row) * 128 + k + 1];
    __nv_bfloat16 h0 = __float2bfloat16_rn(e0);
    __nv_bfloat16 h1 = __float2bfloat16_rn(e1);
    unsigned u0 = *(unsigned short*)&h0, u1 = *(unsigned short*)&h1;
    g_WtFragHi[i] = (u1 << 16) | u0;
}

__global__ void __launch_bounds__(256) wtfrag_lo(const float* __restrict__ Wt) {
    int i = blockIdx.x * 256 + threadIdx.x;
    int q = i & 3, lane = (i >> 2) & 31, ks = (i >> 7) & 7, rb = (i >> 10) & 15, j = i >> 14;
    int row = rb * 16 + (lane >> 2) + (q & 1) * 8;
    int k = ks * 16 + (lane & 3) * 2 + ((q >> 1) & 1) * 8;
    float e0 = Wt[(j * 256 + row) * 128 + k];
    float e1 = Wt[(j * 256 + row) * 128 + k + 1];
    __nv_bfloat16 h0 = __float2bfloat16_rn(e0);
    __nv_bfloat16 h1 = __float2bfloat16_rn(e1);
    __nv_bfloat16 l0 = __float2bfloat16_rn(e0 - __bfloat162float(h0));
    __nv_bfloat16 l1 = __float2bfloat16_rn(e1 - __bfloat162float(h1));
    unsigned u0 = *(unsigned short*)&l0, u1 = *(unsigned short*)&l1;
    g_WtFragLo[i] = (u1 << 16) | u0;
}

// ---------------------------------------------------------------------------
// mma / ldsm helpers
// ---------------------------------------------------------------------------
__device__ __forceinline__ void mma_bf16(float c[4], const unsigned a[4],
                                         unsigned b0, unsigned b1) {
    asm volatile(
        "mma.sync.aligned.m16n8k16.row.col.f32.bf16.bf16.f32 "
        "{%0,%1,%2,%3}, {%4,%5,%6,%7}, {%8,%9}, {%0,%1,%2,%3};"
        : "+f"(c[0]), "+f"(c[1]), "+f"(c[2]), "+f"(c[3])
        : "r"(a[0]), "r"(a[1]), "r"(a[2]), "r"(a[3]), "r"(b0), "r"(b1));
}

__device__ __forceinline__ void ldsm4(unsigned r[4], unsigned saddr) {
    asm volatile(
        "ldmatrix.sync.aligned.m8n8.x4.shared.b16 {%0,%1,%2,%3}, [%4];"
        : "=r"(r[0]), "=r"(r[1]), "=r"(r[2]), "=r"(r[3])
        : "r"(saddr));
}

// ---------------------------------------------------------------------------
// K4: mlp (R11 exact — 32x32 warp tile, REPS=8)
// ---------------------------------------------------------------------------
#define MLP_REPS 8

__global__ void __launch_bounds__(256, 2) mlp_kernel() {
    __shared__ __align__(16) __nv_bfloat16 Whi[128 * 64];
    __shared__ __align__(16) __nv_bfloat16 Bhs[2][64 * 64];
    __shared__ __align__(16) __nv_bfloat16 Bls[2][64 * 64];

    int t = threadIdx.x;
    int lane = t & 31, w = t >> 5;
    int mt = w >> 1;
    int nh = w & 1;
    int combo = blockIdx.y;
    int j = combo % 3;
    int bs = combo / 3;
    int b = bs >> 3, s = bs & 7;
    int g = s - 1 + j;
    g = g < 0 ? 0 : (g > 7 ? 7 : g);

    {
        const uint4* gh = (const uint4*)g_Ws1hi;
        uint4* sh = (uint4*)Whi;
        for (int i = t; i < 1024; i += 256) {
            int r = i >> 3, c = i & 7;
            sh[(r << 3) + (c ^ (r & 7))] = gh[i];
        }
    }
    __syncthreads();

    unsigned sWhi = (unsigned)__cvta_generic_to_shared(Whi);
    unsigned sBh0 = (unsigned)__cvta_generic_to_shared(Bhs[0]);
    unsigned sBl0 = (unsigned)__cvta_generic_to_shared(Bls[0]);

    unsigned ahi[2][4][4];
#pragma unroll
    for (int mi = 0; mi < 2; mi++) {
        int r = mt * 32 + mi * 16 + (lane & 15);
#pragma unroll
        for (int ks = 0; ks < 4; ks++) {
            int chunk = ks * 2 + (lane >> 4);
            ldsm4(ahi[mi][ks], sWhi + r * 128 + ((chunk ^ (r & 7)) << 4));
        }
    }

    int col = t & 63;
    int kq = t >> 6;
    int brow_base = (lane & 7) + ((lane & 16) >> 1);
    int bksel = (lane >> 3) & 1;

    const float4* Pbase = (const float4*)(g_P + (size_t)(b * 8 + g) * Nn * 64);
    const float4* Abase = (const float4*)(g_A + (size_t)bs * Mn * 64);
    const int* idxbase = g_idx + (size_t)combo * Mn * Kn;
    const uint4* fragLoV = (const uint4*)g_WsFragLo;

    float4 pf_p[4];
    int mcur;

    {
        int gcol = blockIdx.x * MLP_REPS * 64 + col;
        mcur = gcol >> 5;
        int knb = gcol & 31;
        int n = idxbase[mcur * Kn + knb];
        const float4* Prow = Pbase + (size_t)n * 16;
#pragma unroll
        for (int q = 0; q < 4; q++) pf_p[q] = Prow[kq * 4 + q];
    }
    {
        const float4* Arow = Abase + (size_t)mcur * 16;
        char* bh = (char*)Bhs[0];
        char* bl = (char*)Bls[0];
#pragma unroll
        for (int q = 0; q < 4; q++) {
            float4 a4 = Arow[kq * 4 + q];
            float h0 = fmaxf(pf_p[q].x - a4.x, 0.f);
            float h1 = fmaxf(pf_p[q].y - a4.y, 0.f);
            float h2 = fmaxf(pf_p[q].z - a4.z, 0.f);
            float h3 = fmaxf(pf_p[q].w - a4.w, 0.f);
            __nv_bfloat162 hiA, hiB, loA, loB;
            hiA.x = __float2bfloat16_rn(h0); hiA.y = __float2bfloat16_rn(h1);
            hiB.x = __float2bfloat16_rn(h2); hiB.y = __float2bfloat16_rn(h3);
            loA.x = __float2bfloat16_rn(h0 - __bfloat162float(hiA.x));
            loA.y = __float2bfloat16_rn(h1 - __bfloat162float(hiA.y));
            loB.x = __float2bfloat16_rn(h2 - __bfloat162float(hiB.x));
            loB.y = __float2bfloat16_rn(h3 - __bfloat162float(hiB.y));
            int k0 = kq * 16 + q * 4;
            int chunk = k0 >> 3;
            int off = col * 128 + ((chunk ^ (col & 7)) << 4) + ((k0 & 7) << 1);
            uint2 vh, vl;
            vh.x = *(unsigned*)&hiA; vh.y = *(unsigned*)&hiB;
            vl.x = *(unsigned*)&loA; vl.y = *(unsigned*)&loB;
            *(uint2*)(bh + off) = vh;
            *(uint2*)(bl + off) = vl;
        }
    }
    __syncthreads();

    for (int rep = 0; rep < MLP_REPS; rep++) {
        int buf = rep & 1;
        int mnext = mcur;
        if (rep + 1 < MLP_REPS) {
            int gcol = (blockIdx.x * MLP_REPS + rep + 1) * 64 + col;
            mnext = gcol >> 5;
            int knb = gcol & 31;
            int n = idxbase[mnext * Kn + knb];
            const float4* Prow = Pbase + (size_t)n * 16;
#pragma unroll
            for (int q = 0; q < 4; q++) pf_p[q] = Prow[kq * 4 + q];
        }

        float acc[2][4][4];
#pragma unroll
        for (int mi = 0; mi < 2; mi++)
#pragma unroll
            for (int nt = 0; nt < 4; nt++)
#pragma unroll
                for (int i = 0; i < 4; i++) acc[mi][nt][i] = 0.f;

        unsigned sBh = sBh0 + buf * 8192;
        unsigned sBl = sBl0 + buf * 8192;
#pragma unroll
        for (int ks = 0; ks < 4; ks++) {
            uint4 fl0 = fragLoV[((mt * 2 + 0) * 4 + ks) * 32 + lane];
            uint4 fl1 = fragLoV[((mt * 2 + 1) * 4 + ks) * 32 + lane];
            unsigned alo0[4] = {fl0.x, fl0.y, fl0.z, fl0.w};
            unsigned alo1[4] = {fl1.x, fl1.y, fl1.z, fl1.w};
            int chunk = ks * 2 + bksel;
#pragma unroll
            for (int p = 0; p < 2; p++) {
                int r = nh * 32 + p * 16 + brow_base;
                unsigned off = r * 128 + ((chunk ^ (r & 7)) << 4);
                unsigned hh[4], ll[4];
                ldsm4(hh, sBh + off);
                ldsm4(ll, sBl + off);
                mma_bf16(acc[0][2 * p],     ahi[0][ks], hh[0], hh[1]);
                mma_bf16(acc[0][2 * p + 1], ahi[0][ks], hh[2], hh[3]);
                mma_bf16(acc[1][2 * p],     ahi[1][ks], hh[0], hh[1]);
                mma_bf16(acc[1][2 * p + 1], ahi[1][ks], hh[2], hh[3]);
                mma_bf16(acc[0][2 * p],     ahi[0][ks], ll[0], ll[1]);
                mma_bf16(acc[0][2 * p + 1], ahi[0][ks], ll[2], ll[3]);
                mma_bf16(acc[1][2 * p],     ahi[1][ks], ll[0], ll[1]);
                mma_bf16(acc[1][2 * p + 1], ahi[1][ks], ll[2], ll[3]);
                mma_bf16(acc[0][2 * p],     alo0,       hh[0], hh[1]);
                mma_bf16(acc[0][2 * p + 1], alo0,       hh[2], hh[3]);
                mma_bf16(acc[1][2 * p],     alo1,       hh[0], hh[1]);
                mma_bf16(acc[1][2 * p + 1], alo1,       hh[2], hh[3]);
            }
        }

        if (rep + 1 < MLP_REPS) {
            const float4* Arow = Abase + (size_t)mnext * 16;
            char* bh = (char*)Bhs[buf ^ 1];
            char* bl = (char*)Bls[buf ^ 1];
#pragma unroll
            for (int q = 0; q < 4; q++) {
                float4 a4 = Arow[kq * 4 + q];
                float h0 = fmaxf(pf_p[q].x - a4.x, 0.f);
                float h1 = fmaxf(pf_p[q].y - a4.y, 0.f);
                float h2 = fmaxf(pf_p[q].z - a4.z, 0.f);
                float h3 = fmaxf(pf_p[q].w - a4.w, 0.f);
                __nv_bfloat162 hiA, hiB, loA, loB;
                hiA.x = __float2bfloat16_rn(h0); hiA.y = __float2bfloat16_rn(h1);
                hiB.x = __float2bfloat16_rn(h2); hiB.y = __float2bfloat16_rn(h3);
                loA.x = __float2bfloat16_rn(h0 - __bfloat162float(hiA.x));
                loA.y = __float2bfloat16_rn(h1 - __bfloat162float(hiA.y));
                loB.x = __float2bfloat16_rn(h2 - __bfloat162float(hiB.x));
                loB.y = __float2bfloat16_rn(h3 - __bfloat162float(hiB.y));
                int k0 = kq * 16 + q * 4;
                int chunk = k0 >> 3;
                int off = col * 128 + ((chunk ^ (col & 7)) << 4) + ((k0 & 7) << 1);
                uint2 vh, vl;
                vh.x = *(unsigned*)&hiA; vh.y = *(unsigned*)&hiB;
                vl.x = *(unsigned*)&loA; vl.y = *(unsigned*)&loB;
                *(uint2*)(bh + off) = vh;
                *(uint2*)(bl + off) = vl;
            }
        }
        mcur = mnext;

        int mbase = (blockIdx.x * MLP_REPS + rep) * 2;
        int grp = lane >> 2;
#pragma unroll
        for (int mi = 0; mi < 2; mi++) {
            float m0 = -1e30f, m1 = -1e30f;
#pragma unroll
            for (int nt = 0; nt < 4; nt++) {
                m0 = fmaxf(m0, fmaxf(acc[mi][nt][0], acc[mi][nt][1]));
                m1 = fmaxf(m1, fmaxf(acc[mi][nt][2], acc[mi][nt][3]));
            }
            m0 = fmaxf(m0, __shfl_xor_sync(0xffffffffu, m0, 1));
            m0 = fmaxf(m0, __shfl_xor_sync(0xffffffffu, m0, 2));
            m1 = fmaxf(m1, __shfl_xor_sync(0xffffffffu, m1, 1));
            m1 = fmaxf(m1, __shfl_xor_sync(0xffffffffu, m1, 2));
            if ((lane & 3) == 0) {
                float* o = g_hmax + ((size_t)combo * Mn + mbase + nh) * 128 +
                           mt * 32 + mi * 16 + grp;
                o[0] = fmaxf(m0, 0.f);
                o[8] = fmaxf(m1, 0.f);
            }
        }
        __syncthreads();
    }
}

// ---------------------------------------------------------------------------
// K5: wt on tensor cores — ONLY change vs R11: __launch_bounds__(256, 2)
// (was reg-limited to 1 CTA/SM at 138 regs, occ 12.4%, issue 15.4%;
// 2 resident CTAs overlap gmem/ldsm latency; smem 33KB allows 6).
// ---------------------------------------------------------------------------
__device__ __forceinline__ void wt_produce(char* bh, char* bl, const float4* pf,
                                           int col, int kq) {
#pragma unroll
    for (int q = 0; q < 4; q++) {
        float4 v = pf[q];
        __nv_bfloat162 hiA, hiB, loA, loB;
        hiA.x = __float2bfloat16_rn(v.x); hiA.y = __float2bfloat16_rn(v.y);
        hiB.x = __float2bfloat16_rn(v.z); hiB.y = __float2bfloat16_rn(v.w);
        loA.x = __float2bfloat16_rn(v.x - __bfloat162float(hiA.x));
        loA.y = __float2bfloat16_rn(v.y - __bfloat162float(hiA.y));
        loB.x = __float2bfloat16_rn(v.z - __bfloat162float(hiB.x));
        loB.y = __float2bfloat16_rn(v.w - __bfloat162float(hiB.y));
        int k0 = kq * 16 + q * 4;
        int chunk = k0 >> 3;
        int off = col * 256 + ((chunk ^ (col & 7)) << 4) + ((k0 & 7) << 1);
        uint2 vh, vl;
        vh.x = *(unsigned*)&hiA; vh.y = *(unsigned*)&hiB;
        vl.x = *(unsigned*)&loA; vl.y = *(unsigned*)&loB;
        *(uint2*)(bh + off) = vh;
        *(uint2*)(bl + off) = vl;
    }
}

__global__ void __launch_bounds__(256, 2) wt_kernel(float* __restrict__ outf) {
    __shared__ __align__(16) __nv_bfloat16 Bh[2][32 * 128];
    __shared__ __align__(16) __nv_bfloat16 Bl[2][32 * 128];

    int t = threadIdx.x;
    int lane = t & 31, w = t >> 5;
    int bs = blockIdx.y;
    int mbase = blockIdx.x * 32;

    int col = t >> 3;
    int kq = t & 7;
    int brow_base = (lane & 7) + ((lane & 16) >> 1);
    int bksel = (lane >> 3) & 1;

    unsigned sBh0 = (unsigned)__cvta_generic_to_shared(Bh[0]);
    unsigned sBl0 = (unsigned)__cvta_generic_to_shared(Bl[0]);

    float4 pf[4];
    {
        const float4* src = (const float4*)(g_hmax +
            (((size_t)(bs * 3 + 0)) * Mn + mbase + col) * 128 + kq * 16);
#pragma unroll
        for (int q = 0; q < 4; q++) pf[q] = src[q];
    }
    wt_produce((char*)Bh[0], (char*)Bl[0], pf, col, kq);
    __syncthreads();

    float tot[2][4][4];
#pragma unroll
    for (int mt = 0; mt < 2; mt++)
#pragma unroll
        for (int nt = 0; nt < 4; nt++)
#pragma unroll
            for (int i = 0; i < 4; i++) tot[mt][nt][i] = 0.f;

    const uint4* fragHi = (const uint4*)g_WtFragHi;
    const uint4* fragLo = (const uint4*)g_WtFragLo;

#pragma unroll
    for (int j = 0; j < 3; j++) {
        if (j < 2) {
            const float4* src = (const float4*)(g_hmax +
                (((size_t)(bs * 3 + j + 1)) * Mn + mbase + col) * 128 + kq * 16);
#pragma unroll
            for (int q = 0; q < 4; q++) pf[q] = src[q];
        }

        float acc[2][4][4];
#pragma unroll
        for (int mt = 0; mt < 2; mt++)
#pragma unroll
            for (int nt = 0; nt < 4; nt++)
#pragma unroll
                for (int i = 0; i < 4; i++) acc[mt][nt][i] = 0.f;

        unsigned sBhj = sBh0 + (j & 1) * 8192;
        unsigned sBlj = sBl0 + (j & 1) * 8192;

#pragma unroll
        for (int ks = 0; ks < 8; ks++) {
            uint4 fh0 = fragHi[((j * 16 + w * 2 + 0) * 8 + ks) * 32 + lane];
            uint4 fl0 = fragLo[((j * 16 + w * 2 + 0) * 8 + ks) * 32 + lane];
            uint4 fh1 = fragHi[((j * 16 + w * 2 + 1) * 8 + ks) * 32 + lane];
            uint4 fl1 = fragLo[((j * 16 + w * 2 + 1) * 8 + ks) * 32 + lane];
            unsigned ah0[4] = {fh0.x, fh0.y, fh0.z, fh0.w};
            unsigned al0[4] = {fl0.x, fl0.y, fl0.z, fl0.w};
            unsigned ah1[4] = {fh1.x, fh1.y, fh1.z, fh1.w};
            unsigned al1[4] = {fl1.x, fl1.y, fl1.z, fl1.w};
            int chunk = ks * 2 + bksel;
#pragma unroll
            for (int p = 0; p < 2; p++) {
                int r = p * 16 + brow_base;
                unsigned off = r * 256 + ((chunk ^ (r & 7)) << 4);
                unsigned hh[4], ll[4];
                ldsm4(hh, sBhj + off);
                ldsm4(ll, sBlj + off);
                mma_bf16(acc[0][2 * p],     ah0, hh[0], hh[1]);
                mma_bf16(acc[0][2 * p],     ah0, ll[0], ll[1]);
                mma_bf16(acc[0][2 * p],     al0, hh[0], hh[1]);
                mma_bf16(acc[0][2 * p + 1], ah0, hh[2], hh[3]);
                mma_bf16(acc[0][2 * p + 1], ah0, ll[2], ll[3]);
                mma_bf16(acc[0][2 * p + 1], al0, hh[2], hh[3]);
                mma_bf16(acc[1][2 * p],     ah1, hh[0], hh[1]);
                mma_bf16(acc[1][2 * p],     ah1, ll[0], ll[1]);
                mma_bf16(acc[1][2 * p],     al1, hh[0], hh[1]);
                mma_bf16(acc[1][2 * p + 1], ah1, hh[2], hh[3]);
                mma_bf16(acc[1][2 * p + 1], ah1, ll[2], ll[3]);
                mma_bf16(acc[1][2 * p + 1], al1, hh[2], hh[3]);
            }
        }

        if (j < 2)
            wt_produce((char*)Bh[(j + 1) & 1], (char*)Bl[(j + 1) & 1], pf, col, kq);

#pragma unroll
        for (int mt = 0; mt < 2; mt++)
#pragma unroll
            for (int nt = 0; nt < 4; nt++)
#pragma unroll
                for (int i = 0; i < 4; i++)
                    tot[mt][nt][i] += fmaxf(acc[mt][nt][i], 0.f);
        __syncthreads();
    }

#pragma unroll
    for (int mt = 0; mt < 2; mt++) {
        int row = w * 32 + mt * 16 + (lane >> 2);
#pragma unroll
        for (int nt = 0; nt < 4; nt++) {
            int c = mbase + nt * 8 + (lane & 3) * 2;
            float2 v0; v0.x = tot[mt][nt][0]; v0.y = tot[mt][nt][1];
            float2 v1; v1.x = tot[mt][nt][2]; v1.y = tot[mt][nt][3];
            *(float2*)&outf[((size_t)bs * 256 + row) * Mn + c] = v0;
            *(float2*)&outf[((size_t)bs * 256 + row + 8) * Mn + c] = v1;
        }
    }
}

// ---------------------------------------------------------------------------
extern "C" void kernel_launch(void* const* d_in, const int* in_sizes, int n_in,
                              void* d_out, int out_size) {
    const float* xyzs = (const float*)d_in[0];
    const float* feats = (const float*)d_in[1];
    const float* Ws0 = (const float*)d_in[2];
    const float* Ws1 = (const float*)d_in[3];
    const float* Wt = (const float*)d_in[4];
    float* out = (float*)d_out;

    const int XYZ_TOTAL = Bn * Sn * Mn * 3;  // 196608

    fps_kernel<<<Bn * Sn, 256>>>(xyzs, out);                         // 1
    compute_PA<<<768, 256>>>(xyzs, feats, Ws0, Ws1);                 // 2
    ball_query_kernel<<<dim3(Mn / 8, Bn * Sn * Jn), 256>>>(xyzs);    // 3
    mlp_kernel<<<dim3(Mn * Kn / (64 * MLP_REPS), Bn * Sn * Jn), 256>>>();  // 4
    wtfrag_hi<<<192, 256>>>(Wt);                                     // 5
    wtfrag_lo<<<192, 256>>>(Wt);                                     // 6
    wt_kernel<<<dim3(Mn / 32, Bn * Sn), 256>>>(out + XYZ_TOTAL);     // 7
}